// round 3
// baseline (speedup 1.0000x reference)
#include <cuda_runtime.h>

#define Bq 8
#define Sq 4096
#define Dq 512
#define Mq 16
#define NCH 32
#define SCH (Sq/NCH)          // 128
#define INV_S (1.0f/4096.0f)

// ---------------- device scratch (no allocations allowed) ----------------
__device__ float2 g_tw[Sq*Mq];            // per (s,k): (cos(w_k s), -sin(w_k s))
__device__ float  g_mu[Bq*Sq];
__device__ float  g_rs[Bq*Sq];
__device__ float  g_part[NCH*Bq*2*Mq*Dq]; // partial projections [chunk][b][re/im][k][d]
__device__ float  g_D[Bq*2*Mq*Dq];        // spectral coeffs with w applied [b][re/im][k][d]
__device__ float  g_xsf[Bq*Dq];           // xs at s=0   (scaled by 1/S)
__device__ float  g_xsl[Bq*Dq];           // xs at s=S-1 (scaled by 1/S)
__device__ float2 g_A[Bq*Mq*Dq];          // combined scaled coeffs [b][k][d]
__device__ float  g_c0[Bq*Dq];            // boundary correction at s=0
__device__ float  g_cN[Bq*Dq];            // boundary correction at s=S-1

// ---------------- twiddle table ----------------
__global__ void twiddle_k() {
    int i = blockIdx.x * 256 + threadIdx.x;   // i = s*16 + k
    int s = i >> 4, k = i & 15;
    int ks = (k * s) & (Sq - 1);
    double arg = (double)ks * (6.283185307179586476925286766559 / (double)Sq);
    double sd, cd;
    sincos(arg, &sd, &cd);
    g_tw[i] = make_float2((float)cd, (float)(-sd));
}

// ---------------- LayerNorm stats: one warp per (b,s) row ----------------
__global__ void ln_k(const float* __restrict__ x) {
    int lane = threadIdx.x & 31;
    int row  = blockIdx.x * 8 + (threadIdx.x >> 5);   // b*Sq + s
    const float4* xr = (const float4*)(x + (size_t)row * Dq);
    float s1 = 0.f, s2 = 0.f;
#pragma unroll
    for (int it = 0; it < 4; it++) {
        float4 v = xr[lane + it * 32];
        s1 += (v.x + v.y) + (v.z + v.w);
        s2 = fmaf(v.x, v.x, s2); s2 = fmaf(v.y, v.y, s2);
        s2 = fmaf(v.z, v.z, s2); s2 = fmaf(v.w, v.w, s2);
    }
#pragma unroll
    for (int off = 16; off > 0; off >>= 1) {
        s1 += __shfl_xor_sync(0xffffffffu, s1, off);
        s2 += __shfl_xor_sync(0xffffffffu, s2, off);
    }
    if (lane == 0) {
        float mu  = s1 * (1.f / Dq);
        float var = fmaf(-mu, mu, s2 * (1.f / Dq));
        g_mu[row] = mu;
        g_rs[row] = rsqrtf(var + 1e-5f);
    }
}

// ---------------- projection: P_k[b,d] = sum_s xn * e^{-i w_k s} (partials) ----------------
__global__ void proj_k(const float* __restrict__ x,
                       const float* __restrict__ gamma,
                       const float* __restrict__ beta) {
    __shared__ unsigned long long stw[SCH * Mq];   // 16 KB
    __shared__ float smu[SCH], srs[SCH];
    int b = blockIdx.y, ch = blockIdx.x, d = threadIdx.x;
    int s0 = ch * SCH;
    const unsigned long long* twp = (const unsigned long long*)g_tw + (size_t)s0 * Mq;
    for (int i = d; i < SCH * Mq; i += Dq) stw[i] = twp[i];
    if (d < SCH) { smu[d] = g_mu[b * Sq + s0 + d]; srs[d] = g_rs[b * Sq + s0 + d]; }
    __syncthreads();

    float gm = gamma[d], bt = beta[d];
    unsigned long long acc[Mq];
#pragma unroll
    for (int k = 0; k < Mq; k++) acc[k] = 0ull;   // bit pattern of (0.f, 0.f)

    const float* xp = x + ((size_t)(b * Sq + s0)) * Dq + d;
#pragma unroll 2
    for (int i = 0; i < SCH; i++) {
        float xn = fmaf((xp[i * Dq] - smu[i]) * srs[i], gm, bt);
        unsigned long long xnp;
        asm("mov.b64 %0, {%1, %1};" : "=l"(xnp) : "f"(xn));
#pragma unroll
        for (int k = 0; k < Mq; k++) {
            asm("fma.rn.f32x2 %0, %1, %2, %0;" : "+l"(acc[k]) : "l"(xnp), "l"(stw[i * Mq + k]));
        }
    }
    int base = ((ch * Bq + b) * 2) * (Mq * Dq) + d;
#pragma unroll
    for (int k = 0; k < Mq; k++) {
        float re, im;
        asm("mov.b64 {%0, %1}, %2;" : "=f"(re), "=f"(im) : "l"(acc[k]));
        g_part[base + k * Dq]           = re;   // Re P
        g_part[base + Mq * Dq + k * Dq] = im;   // Im P (already -sum xn sin)
    }
}

// ---------------- reduce partials, apply complex spectral weight ----------------
__global__ void c0a_k(const float* __restrict__ wr, const float* __restrict__ wi) {
    int k = blockIdx.x, b = blockIdx.y, d = threadIdx.x;
    float sr = 0.f, si = 0.f;
#pragma unroll 4
    for (int c = 0; c < NCH; c++) {
        int base = ((c * Bq + b) * 2) * (Mq * Dq) + k * Dq + d;
        sr += g_part[base];
        si += g_part[base + Mq * Dq];
    }
    float wrv = wr[d * Mq + k], wiv = wi[d * Mq + k];
    float Dr = sr * wrv - si * wiv;
    float Di = (k == 0) ? 0.f : fmaf(sr, wiv, si * wrv);   // irfft drops Im of bin 0
    g_D[(b * 2    ) * (Mq * Dq) + k * Dq + d] = Dr;
    g_D[(b * 2 + 1) * (Mq * Dq) + k * Dq + d] = Di;
}

// ---------------- edge values xs(0), xs(S-1) ----------------
__global__ void c0b_k() {
    int b = blockIdx.x, di = threadIdx.x;
    float xsf = 0.f, xsl = 0.f;
#pragma unroll
    for (int k = 0; k < Mq; k++) {
        float Dr = g_D[(b * 2    ) * (Mq * Dq) + k * Dq + di];
        float Di = g_D[(b * 2 + 1) * (Mq * Dq) + k * Dq + di];
        float2 t = g_tw[Mq + k];           // s=1 row: (cos w_k, -sin w_k)
        float ck = t.x, sk = -t.y;
        float m = (k == 0) ? 1.f : 2.f;
        xsf += m * Dr;
        xsl += m * (Dr * ck + Di * sk);    // Re(D_k e^{-i w_k})
    }
    g_xsf[b * Dq + di] = xsf * INV_S;
    g_xsl[b * Dq + di] = xsl * INV_S;
}

// ---------------- spectral-domain conv: A_k = D_k + H_k * D_k, plus edge corrections ----------------
// grid (4 kgroups, 4 do-tiles, B), block 128 (one 'do' per thread)
__global__ void c1_k(const float* __restrict__ cw) {
    int kg = blockIdx.x, tile = blockIdx.y, b = blockIdx.z;
    int tid = threadIdx.x;
    int dd = tile * 128 + tid;
    int k0 = kg * 4;
    __shared__ float sDr[4][128], sDi[4][128], sxf[128], sxl[128];

    float ck[4], sk[4];
#pragma unroll
    for (int kk = 0; kk < 4; kk++) {
        float2 t = g_tw[Mq + (k0 + kk)];
        ck[kk] = t.x; sk[kk] = -t.y;
    }
    float ar[4] = {0.f, 0.f, 0.f, 0.f}, ai[4] = {0.f, 0.f, 0.f, 0.f};
    float a0 = 0.f, aN = 0.f;

    for (int c = 0; c < 4; c++) {
        __syncthreads();
#pragma unroll
        for (int kk = 0; kk < 4; kk++) {
            sDr[kk][tid] = g_D[(b * 2    ) * (Mq * Dq) + (k0 + kk) * Dq + c * 128 + tid];
            sDi[kk][tid] = g_D[(b * 2 + 1) * (Mq * Dq) + (k0 + kk) * Dq + c * 128 + tid];
        }
        if (kg == 0) {
            sxf[tid] = g_xsf[b * Dq + c * 128 + tid];
            sxl[tid] = g_xsl[b * Dq + c * 128 + tid];
        }
        __syncthreads();
        const float* wrow = cw + ((size_t)dd * Dq + c * 128) * 3;
#pragma unroll 4
        for (int j = 0; j < 128; j++) {
            float w0 = wrow[j * 3 + 0], w1 = wrow[j * 3 + 1], w2 = wrow[j * 3 + 2];
            float ws = w0 + w2, wd = w2 - w0;
#pragma unroll
            for (int kk = 0; kk < 4; kk++) {
                float hr = fmaf(ws, ck[kk], w1);
                float hi = wd * sk[kk];
                float Dr = sDr[kk][j], Di = sDi[kk][j];
                ar[kk] = fmaf(hr, Dr, ar[kk]); ar[kk] = fmaf(-hi, Di, ar[kk]);
                ai[kk] = fmaf(hr, Di, ai[kk]); ai[kk] = fmaf( hi, Dr, ai[kk]);
            }
            if (kg == 0) {
                a0 = fmaf(-w0, sxl[j], a0);   // circular wrap removal at s=0
                aN = fmaf(-w2, sxf[j], aN);   // circular wrap removal at s=S-1
            }
        }
    }
#pragma unroll
    for (int kk = 0; kk < 4; kk++) {
        int k = k0 + kk;
        float Drn = g_D[(b * 2    ) * (Mq * Dq) + k * Dq + dd];
        float Din = g_D[(b * 2 + 1) * (Mq * Dq) + k * Dq + dd];
        float sc = (k == 0) ? INV_S : 2.f * INV_S;
        g_A[(b * Mq + k) * Dq + dd] = make_float2(sc * (ar[kk] + Drn), sc * (ai[kk] + Din));
    }
    if (kg == 0) {
        g_c0[b * Dq + dd] = a0;
        g_cN[b * Dq + dd] = aN;
    }
}

// ---------------- final: out = x + conv_b + basis reconstruction + edge corrections ----------------
__global__ void final_k(const float* __restrict__ x, const float* __restrict__ cb,
                        float* __restrict__ out) {
    __shared__ unsigned long long stw[SCH * Mq];
    int b = blockIdx.y, ch = blockIdx.x, d = threadIdx.x;
    int s0 = ch * SCH;
    const unsigned long long* twp = (const unsigned long long*)g_tw + (size_t)s0 * Mq;
    for (int i = d; i < SCH * Mq; i += Dq) stw[i] = twp[i];
    __syncthreads();

    unsigned long long a[Mq];
    const unsigned long long* Ap = (const unsigned long long*)g_A + (size_t)b * Mq * Dq + d;
#pragma unroll
    for (int k = 0; k < Mq; k++) a[k] = Ap[k * Dq];

    float base_add = cb[d];
    float c0v = g_c0[b * Dq + d], cNv = g_cN[b * Dq + d];
    const float* xp = x   + ((size_t)(b * Sq + s0)) * Dq + d;
    float*       op = out + ((size_t)(b * Sq + s0)) * Dq + d;

#pragma unroll 2
    for (int i = 0; i < SCH; i++) {
        unsigned long long acc;
        asm("mul.rn.f32x2 %0, %1, %2;" : "=l"(acc) : "l"(a[0]), "l"(stw[i * Mq]));
#pragma unroll
        for (int k = 1; k < Mq; k++) {
            asm("fma.rn.f32x2 %0, %1, %2, %0;" : "+l"(acc) : "l"(a[k]), "l"(stw[i * Mq + k]));
        }
        float rx, ry;
        asm("mov.b64 {%0, %1}, %2;" : "=f"(rx), "=f"(ry) : "l"(acc));
        float v = xp[i * Dq] + base_add + (rx + ry);
        int s = s0 + i;
        if (s == 0)      v += c0v;
        if (s == Sq - 1) v += cNv;
        op[i * Dq] = v;
    }
}

// ---------------- launch ----------------
extern "C" void kernel_launch(void* const* d_in, const int* in_sizes, int n_in,
                              void* d_out, int out_size) {
    (void)in_sizes; (void)n_in; (void)out_size;
    const float* x     = (const float*)d_in[0];
    const float* gamma = (const float*)d_in[1];
    const float* beta  = (const float*)d_in[2];
    const float* wr    = (const float*)d_in[3];
    const float* wi    = (const float*)d_in[4];
    const float* cw    = (const float*)d_in[5];
    const float* cb    = (const float*)d_in[6];
    float* out = (float*)d_out;

    twiddle_k<<<(Sq * Mq) / 256, 256>>>();
    ln_k<<<(Bq * Sq) / 8, 256>>>(x);
    proj_k<<<dim3(NCH, Bq), Dq>>>(x, gamma, beta);
    c0a_k<<<dim3(Mq, Bq), Dq>>>(wr, wi);
    c0b_k<<<Bq, Dq>>>();
    c1_k<<<dim3(4, 4, Bq), 128>>>(cw);
    final_k<<<dim3(NCH, Bq), Dq>>>(x, cb, out);
}

// round 4
// speedup vs baseline: 2.4033x; 2.4033x over previous
#include <cuda_runtime.h>

#define Bq 8
#define Sq 4096
#define Dq 512
#define Mq 16
#define NCH 32
#define SCH (Sq/NCH)          // 128
#define INV_S (1.0f/4096.0f)

// ---------------- device scratch (no allocations allowed) ----------------
__device__ __align__(16) float2 g_tw[Sq*Mq];   // per (s,k): (cos(w_k s), -sin(w_k s))
__device__ float  g_mu[Bq*Sq];
__device__ float  g_rs[Bq*Sq];
__device__ float2 g_part[NCH*Bq*Mq*Dq];        // partial projections [chunk][b][k][d] (re,im)
__device__ float2 g_D[Bq*Mq*Dq];               // spectral coeffs with w applied [b][k][d]
__device__ float  g_xsf[Bq*Dq];                // xs at s=0   (scaled by 1/S)
__device__ float  g_xsl[Bq*Dq];                // xs at s=S-1 (scaled by 1/S)
__device__ float2 g_A[Bq*Mq*Dq];               // combined scaled coeffs [b][k][d]
__device__ float  g_c0[Bq*Dq];                 // boundary correction at s=0
__device__ float  g_cN[Bq*Dq];                 // boundary correction at s=S-1
// transposed conv weights, [di][dd] layout (coalesced along dd)
__device__ float  g_w1[Dq*Dq];
__device__ float  g_ws[Dq*Dq];                 // w0+w2
__device__ float  g_wd[Dq*Dq];                 // w2-w0
// c1 partials over di-chunks
__device__ float2 g_c1p[4*Bq*Mq*Dq];           // [cc][b][k][dd]
__device__ float2 g_edg[4*Bq*Dq];              // [cc][b][dd] -> (a0, aN)

// ---------------- twiddle table (float sincospi: exact argument) ----------------
__global__ void twiddle_k() {
    int i = blockIdx.x * 256 + threadIdx.x;   // i = s*16 + k
    int s = i >> 4, k = i & 15;
    int ks = (k * s) & (Sq - 1);
    float sf, cf;
    sincospif((float)ks * (1.0f / 2048.0f), &sf, &cf);
    g_tw[i] = make_float2(cf, -sf);
}

// ---------------- transpose conv weights into [di][dd] planes ----------------
__global__ void tr_k(const float* __restrict__ cw) {
    __shared__ float t1[32][33], ts[32][33], td[32][33];
    int di0 = blockIdx.x * 32, dd0 = blockIdx.y * 32;
    int tx = threadIdx.x, ty = threadIdx.y;   // block (32,8)
#pragma unroll
    for (int jj = 0; jj < 4; jj++) {
        int ddl = ty + jj * 8;
        const float* p = cw + ((size_t)(dd0 + ddl) * Dq + di0 + tx) * 3;
        float w0 = p[0], w1 = p[1], w2 = p[2];
        t1[ddl][tx] = w1;
        ts[ddl][tx] = w0 + w2;
        td[ddl][tx] = w2 - w0;
    }
    __syncthreads();
#pragma unroll
    for (int jj = 0; jj < 4; jj++) {
        int dil = ty + jj * 8;
        size_t o = (size_t)(di0 + dil) * Dq + dd0 + tx;
        g_w1[o] = t1[tx][dil];
        g_ws[o] = ts[tx][dil];
        g_wd[o] = td[tx][dil];
    }
}

// ---------------- LayerNorm stats: one warp per (b,s) row ----------------
__global__ void ln_k(const float* __restrict__ x) {
    int lane = threadIdx.x & 31;
    int row  = blockIdx.x * 8 + (threadIdx.x >> 5);   // b*Sq + s
    const float4* xr = (const float4*)(x + (size_t)row * Dq);
    float s1 = 0.f, s2 = 0.f;
#pragma unroll
    for (int it = 0; it < 4; it++) {
        float4 v = xr[lane + it * 32];
        s1 += (v.x + v.y) + (v.z + v.w);
        s2 = fmaf(v.x, v.x, s2); s2 = fmaf(v.y, v.y, s2);
        s2 = fmaf(v.z, v.z, s2); s2 = fmaf(v.w, v.w, s2);
    }
#pragma unroll
    for (int off = 16; off > 0; off >>= 1) {
        s1 += __shfl_xor_sync(0xffffffffu, s1, off);
        s2 += __shfl_xor_sync(0xffffffffu, s2, off);
    }
    if (lane == 0) {
        float mu  = s1 * (1.f / Dq);
        float var = fmaf(-mu, mu, s2 * (1.f / Dq));
        g_mu[row] = mu;
        g_rs[row] = rsqrtf(var + 1e-5f);
    }
}

// ---------------- projection: P_k[b,d] = sum_s xn * e^{-i w_k s} (partials) ----------------
__global__ void proj_k(const float* __restrict__ x,
                       const float* __restrict__ gamma,
                       const float* __restrict__ beta) {
    __shared__ ulonglong2 stw[SCH * Mq / 2];   // 16 KB, LDS.128 staging
    __shared__ float smu[SCH], srs[SCH];
    int b = blockIdx.y, ch = blockIdx.x, d = threadIdx.x;
    int s0 = ch * SCH;
    const ulonglong2* twp = (const ulonglong2*)(g_tw + (size_t)s0 * Mq);
    for (int i = d; i < SCH * Mq / 2; i += Dq) stw[i] = twp[i];
    if (d < SCH) { smu[d] = g_mu[b * Sq + s0 + d]; srs[d] = g_rs[b * Sq + s0 + d]; }
    __syncthreads();

    float gm = gamma[d], bt = beta[d];
    unsigned long long acc[Mq];
#pragma unroll
    for (int k = 0; k < Mq; k++) acc[k] = 0ull;

    const float* xp = x + ((size_t)(b * Sq + s0)) * Dq + d;
#pragma unroll 2
    for (int i = 0; i < SCH; i++) {
        float xn = fmaf((xp[i * Dq] - smu[i]) * srs[i], gm, bt);
        unsigned long long xnp;
        asm("mov.b64 %0, {%1, %1};" : "=l"(xnp) : "f"(xn));
#pragma unroll
        for (int k2 = 0; k2 < 8; k2++) {
            ulonglong2 t = stw[i * 8 + k2];
            asm("fma.rn.f32x2 %0, %1, %2, %0;" : "+l"(acc[2*k2  ]) : "l"(xnp), "l"(t.x));
            asm("fma.rn.f32x2 %0, %1, %2, %0;" : "+l"(acc[2*k2+1]) : "l"(xnp), "l"(t.y));
        }
    }
    unsigned long long* pout = (unsigned long long*)g_part + ((size_t)(ch * Bq + b) * Mq) * Dq + d;
#pragma unroll
    for (int k = 0; k < Mq; k++) pout[k * Dq] = acc[k];
}

// ---------------- reduce partials, apply complex spectral weight ----------------
__global__ void c0a_k(const float* __restrict__ wr, const float* __restrict__ wi) {
    int k = blockIdx.x, b = blockIdx.y;
    int d = blockIdx.z * 128 + threadIdx.x;
    const unsigned long long* pp = (const unsigned long long*)g_part;
    unsigned long long s = 0ull;
#pragma unroll
    for (int c = 0; c < NCH; c++) {
        unsigned long long v = pp[((size_t)(c * Bq + b) * Mq + k) * Dq + d];
        asm("add.rn.f32x2 %0, %0, %1;" : "+l"(s) : "l"(v));
    }
    float sr, si;
    asm("mov.b64 {%0, %1}, %2;" : "=f"(sr), "=f"(si) : "l"(s));
    float wrv = wr[d * Mq + k], wiv = wi[d * Mq + k];
    float Dr = sr * wrv - si * wiv;
    float Di = (k == 0) ? 0.f : fmaf(sr, wiv, si * wrv);   // irfft drops Im of bin 0
    g_D[(size_t)(b * Mq + k) * Dq + d] = make_float2(Dr, Di);
}

// ---------------- edge values xs(0), xs(S-1) ----------------
__global__ void c0b_k() {
    int b = blockIdx.x, di = threadIdx.x;
    float xsf = 0.f, xsl = 0.f;
#pragma unroll
    for (int k = 0; k < Mq; k++) {
        float2 Dv = g_D[(size_t)(b * Mq + k) * Dq + di];
        float2 t = g_tw[Mq + k];           // s=1 row: (cos w_k, -sin w_k)
        float ck = t.x, sk = -t.y;
        float m = (k == 0) ? 1.f : 2.f;
        xsf += m * Dv.x;
        xsl += m * (Dv.x * ck + Dv.y * sk);    // Re(D_k e^{-i w_k})
    }
    g_xsf[b * Dq + di] = xsf * INV_S;
    g_xsl[b * Dq + di] = xsl * INV_S;
}

// ---------------- spectral-domain conv partials: coalesced, split over di chunks ----------------
// grid (16 = kg*? no: x = cc*4+kg, y = do-tile(4), z = b(8)), block 128
__global__ void c1_k() {
    int kg = blockIdx.x & 3, cc = blockIdx.x >> 2;
    int tile = blockIdx.y, b = blockIdx.z;
    int tid = threadIdx.x;
    int dd = tile * 128 + tid;
    int k0 = kg * 4;
    __shared__ float sDr[4][128], sDi[4][128], sxf[128], sxl[128];

    float ck[4], sk[4];
#pragma unroll
    for (int kk = 0; kk < 4; kk++) {
        float2 t = g_tw[Mq + (k0 + kk)];
        ck[kk] = t.x; sk[kk] = -t.y;
    }
#pragma unroll
    for (int kk = 0; kk < 4; kk++) {
        float2 Dv = g_D[(size_t)(b * Mq + k0 + kk) * Dq + cc * 128 + tid];
        sDr[kk][tid] = Dv.x; sDi[kk][tid] = Dv.y;
    }
    if (kg == 0) {
        sxf[tid] = g_xsf[b * Dq + cc * 128 + tid];
        sxl[tid] = g_xsl[b * Dq + cc * 128 + tid];
    }
    __syncthreads();

    float ar[4] = {0.f,0.f,0.f,0.f}, ai[4] = {0.f,0.f,0.f,0.f};
    float a0 = 0.f, aN = 0.f;
    int dibase = cc * 128;
#pragma unroll 4
    for (int j = 0; j < 128; j++) {
        size_t o = (size_t)(dibase + j) * Dq + dd;
        float w1 = g_w1[o], ws = g_ws[o], wd = g_wd[o];
#pragma unroll
        for (int kk = 0; kk < 4; kk++) {
            float hr = fmaf(ws, ck[kk], w1);
            float hi = wd * sk[kk];
            float Dr = sDr[kk][j], Di = sDi[kk][j];
            ar[kk] = fmaf(hr, Dr, ar[kk]); ar[kk] = fmaf(-hi, Di, ar[kk]);
            ai[kk] = fmaf(hr, Di, ai[kk]); ai[kk] = fmaf( hi, Dr, ai[kk]);
        }
        if (kg == 0) {
            float w0 = 0.5f * (ws - wd), w2 = 0.5f * (ws + wd);
            a0 = fmaf(-w0, sxl[j], a0);   // circular wrap removal at s=0
            aN = fmaf(-w2, sxf[j], aN);   // circular wrap removal at s=S-1
        }
    }
#pragma unroll
    for (int kk = 0; kk < 4; kk++)
        g_c1p[((size_t)(cc * Bq + b) * Mq + k0 + kk) * Dq + dd] = make_float2(ar[kk], ai[kk]);
    if (kg == 0)
        g_edg[(size_t)(cc * Bq + b) * Dq + dd] = make_float2(a0, aN);
}

// ---------------- reduce c1 partials: A_k = sc*(conv + identity), edge sums ----------------
__global__ void c1r_k() {
    int k = blockIdx.x, b = blockIdx.y, d = threadIdx.x;
    float sr = 0.f, si = 0.f;
#pragma unroll
    for (int cc = 0; cc < 4; cc++) {
        float2 v = g_c1p[((size_t)(cc * Bq + b) * Mq + k) * Dq + d];
        sr += v.x; si += v.y;
    }
    float2 Dv = g_D[(size_t)(b * Mq + k) * Dq + d];
    float sc = (k == 0) ? INV_S : 2.f * INV_S;
    g_A[(size_t)(b * Mq + k) * Dq + d] = make_float2(sc * (sr + Dv.x), sc * (si + Dv.y));
    if (k == 0) {
        float e0 = 0.f, eN = 0.f;
#pragma unroll
        for (int cc = 0; cc < 4; cc++) {
            float2 e = g_edg[(size_t)(cc * Bq + b) * Dq + d];
            e0 += e.x; eN += e.y;
        }
        g_c0[b * Dq + d] = e0;
        g_cN[b * Dq + d] = eN;
    }
}

// ---------------- final: out = x + conv_b + basis reconstruction + edge corrections ----------------
__global__ void final_k(const float* __restrict__ x, const float* __restrict__ cb,
                        float* __restrict__ out) {
    __shared__ ulonglong2 stw[SCH * Mq / 2];
    int b = blockIdx.y, ch = blockIdx.x, d = threadIdx.x;
    int s0 = ch * SCH;
    const ulonglong2* twp = (const ulonglong2*)(g_tw + (size_t)s0 * Mq);
    for (int i = d; i < SCH * Mq / 2; i += Dq) stw[i] = twp[i];
    __syncthreads();

    unsigned long long a[Mq];
    const unsigned long long* Ap = (const unsigned long long*)g_A + (size_t)b * Mq * Dq + d;
#pragma unroll
    for (int k = 0; k < Mq; k++) a[k] = Ap[k * Dq];

    float base_add = cb[d];
    float c0v = g_c0[b * Dq + d], cNv = g_cN[b * Dq + d];
    const float* xp = x   + ((size_t)(b * Sq + s0)) * Dq + d;
    float*       op = out + ((size_t)(b * Sq + s0)) * Dq + d;

#pragma unroll 2
    for (int i = 0; i < SCH; i++) {
        unsigned long long acc;
        {
            ulonglong2 t = stw[i * 8];
            asm("mul.rn.f32x2 %0, %1, %2;" : "=l"(acc) : "l"(a[0]), "l"(t.x));
            asm("fma.rn.f32x2 %0, %1, %2, %0;" : "+l"(acc) : "l"(a[1]), "l"(t.y));
        }
#pragma unroll
        for (int k2 = 1; k2 < 8; k2++) {
            ulonglong2 t = stw[i * 8 + k2];
            asm("fma.rn.f32x2 %0, %1, %2, %0;" : "+l"(acc) : "l"(a[2*k2  ]), "l"(t.x));
            asm("fma.rn.f32x2 %0, %1, %2, %0;" : "+l"(acc) : "l"(a[2*k2+1]), "l"(t.y));
        }
        float rx, ry;
        asm("mov.b64 {%0, %1}, %2;" : "=f"(rx), "=f"(ry) : "l"(acc));
        float v = xp[i * Dq] + base_add + (rx + ry);
        int s = s0 + i;
        if (s == 0)      v += c0v;
        if (s == Sq - 1) v += cNv;
        op[i * Dq] = v;
    }
}

// ---------------- launch ----------------
extern "C" void kernel_launch(void* const* d_in, const int* in_sizes, int n_in,
                              void* d_out, int out_size) {
    (void)in_sizes; (void)n_in; (void)out_size;
    const float* x     = (const float*)d_in[0];
    const float* gamma = (const float*)d_in[1];
    const float* beta  = (const float*)d_in[2];
    const float* wr    = (const float*)d_in[3];
    const float* wi    = (const float*)d_in[4];
    const float* cw    = (const float*)d_in[5];
    const float* cb    = (const float*)d_in[6];
    float* out = (float*)d_out;

    twiddle_k<<<(Sq * Mq) / 256, 256>>>();
    tr_k<<<dim3(Dq / 32, Dq / 32), dim3(32, 8)>>>(cw);
    ln_k<<<(Bq * Sq) / 8, 256>>>(x);
    proj_k<<<dim3(NCH, Bq), Dq>>>(x, gamma, beta);
    c0a_k<<<dim3(Mq, Bq, 4), 128>>>(wr, wi);
    c0b_k<<<Bq, Dq>>>();
    c1_k<<<dim3(16, 4, Bq), 128>>>();
    c1r_k<<<dim3(Mq, Bq), Dq>>>();
    final_k<<<dim3(NCH, Bq), Dq>>>(x, cb, out);
}

// round 5
// speedup vs baseline: 2.7684x; 1.1519x over previous
#include <cuda_runtime.h>

#define Bq 8
#define Sq 4096
#define Hq 2048               // half period
#define Dq 512
#define Mq 16
#define NCH 32
#define SCH (Hq/NCH)          // 64 s_lo rows per chunk
#define INV_S (1.0f/4096.0f)

// ---------------- device scratch (no allocations allowed) ----------------
__device__ __align__(16) float2 g_tw[Hq*Mq];   // per (s,k), s<2048: (cos(w_k s), -sin(w_k s))
__device__ float  g_mu[Bq*Sq];
__device__ float  g_rs[Bq*Sq];
__device__ float2 g_part[NCH*Bq*Mq*Dq];        // partial projections [chunk][b][k][d] (re,im)
__device__ float2 g_D[Bq*Mq*Dq];               // spectral coeffs with w applied [b][k][d]
__device__ float  g_xsf[Bq*Dq];                // xs at s=0   (scaled by 1/S)
__device__ float  g_xsl[Bq*Dq];                // xs at s=S-1 (scaled by 1/S)
__device__ float2 g_A[Bq*Mq*Dq];               // combined scaled coeffs [b][k][d]
__device__ float  g_c0[Bq*Dq];                 // boundary correction at s=0
__device__ float  g_cN[Bq*Dq];                 // boundary correction at s=S-1
// transposed conv weights, [di][dd] layout (coalesced along dd)
__device__ float  g_w1[Dq*Dq];
__device__ float  g_ws[Dq*Dq];                 // w0+w2
__device__ float  g_wd[Dq*Dq];                 // w2-w0
// c1 partials over di-chunks
__device__ float2 g_c1p[4*Bq*Mq*Dq];           // [cc][b][k][dd]
__device__ float2 g_edg[4*Bq*Dq];              // [cc][b][dd] -> (a0, aN)

// ---------------- twiddle table (float sincospi: exact argument) ----------------
__global__ void twiddle_k() {
    int i = blockIdx.x * 256 + threadIdx.x;   // i = s*16 + k, s < 2048
    int s = i >> 4, k = i & 15;
    int ks = (k * s) & (Sq - 1);
    float sf, cf;
    sincospif((float)ks * (1.0f / 2048.0f), &sf, &cf);
    g_tw[i] = make_float2(cf, -sf);
}

// ---------------- transpose conv weights into [di][dd] planes ----------------
__global__ void tr_k(const float* __restrict__ cw) {
    __shared__ float t1[32][33], ts[32][33], td[32][33];
    int di0 = blockIdx.x * 32, dd0 = blockIdx.y * 32;
    int tx = threadIdx.x, ty = threadIdx.y;   // block (32,8)
#pragma unroll
    for (int jj = 0; jj < 4; jj++) {
        int ddl = ty + jj * 8;
        const float* p = cw + ((size_t)(dd0 + ddl) * Dq + di0 + tx) * 3;
        float w0 = p[0], w1 = p[1], w2 = p[2];
        t1[ddl][tx] = w1;
        ts[ddl][tx] = w0 + w2;
        td[ddl][tx] = w2 - w0;
    }
    __syncthreads();
#pragma unroll
    for (int jj = 0; jj < 4; jj++) {
        int dil = ty + jj * 8;
        size_t o = (size_t)(di0 + dil) * Dq + dd0 + tx;
        g_w1[o] = t1[tx][dil];
        g_ws[o] = ts[tx][dil];
        g_wd[o] = td[tx][dil];
    }
}

// ---------------- LayerNorm stats: one warp per (b,s) row ----------------
__global__ void ln_k(const float* __restrict__ x) {
    int lane = threadIdx.x & 31;
    int row  = blockIdx.x * 8 + (threadIdx.x >> 5);   // b*Sq + s
    const float4* xr = (const float4*)(x + (size_t)row * Dq);
    float s1 = 0.f, s2 = 0.f;
#pragma unroll
    for (int it = 0; it < 4; it++) {
        float4 v = xr[lane + it * 32];
        s1 += (v.x + v.y) + (v.z + v.w);
        s2 = fmaf(v.x, v.x, s2); s2 = fmaf(v.y, v.y, s2);
        s2 = fmaf(v.z, v.z, s2); s2 = fmaf(v.w, v.w, s2);
    }
#pragma unroll
    for (int off = 16; off > 0; off >>= 1) {
        s1 += __shfl_xor_sync(0xffffffffu, s1, off);
        s2 += __shfl_xor_sync(0xffffffffu, s2, off);
    }
    if (lane == 0) {
        float mu  = s1 * (1.f / Dq);
        float var = fmaf(-mu, mu, s2 * (1.f / Dq));
        g_mu[row] = mu;
        g_rs[row] = rsqrtf(var + 1e-5f);
    }
}

// ---------------- projection with half-period pairing ----------------
// pair (s, s+2048): P_k += (xn_a + (-1)^k xn_b) * e^{-i w_k s}
// grid (NCH, Bq, 2 d-tiles), block 256
__global__ void __launch_bounds__(256) proj_k(const float* __restrict__ x,
                       const float* __restrict__ gamma,
                       const float* __restrict__ beta) {
    __shared__ ulonglong2 stw[SCH * Mq / 2];   // 8 KB
    __shared__ float smu[2 * SCH], srs[2 * SCH];
    int b = blockIdx.y, ch = blockIdx.x;
    int d = blockIdx.z * 256 + threadIdx.x;
    int t = threadIdx.x;
    int s0 = ch * SCH;
    const ulonglong2* twp = (const ulonglong2*)(g_tw + (size_t)s0 * Mq);
#pragma unroll
    for (int i = t; i < SCH * Mq / 2; i += 256) stw[i] = twp[i];
    int row0 = b * Sq + s0;
    if (t < SCH)            { smu[t] = g_mu[row0 + t];             srs[t] = g_rs[row0 + t]; }
    else if (t < 2 * SCH)   { smu[t] = g_mu[row0 + Hq + (t - SCH)]; srs[t] = g_rs[row0 + Hq + (t - SCH)]; }
    __syncthreads();

    float gm = gamma[d], bt = beta[d];
    unsigned long long acc[Mq];
#pragma unroll
    for (int k = 0; k < Mq; k++) acc[k] = 0ull;

    const float* xa = x + ((size_t)row0) * Dq + d;
    const float* xb = xa + (size_t)Hq * Dq;
    for (int i0 = 0; i0 < SCH; i0 += 4) {
        float va[4], vb[4];
#pragma unroll
        for (int u = 0; u < 4; u++) { va[u] = xa[(i0 + u) * Dq]; vb[u] = xb[(i0 + u) * Dq]; }
#pragma unroll
        for (int u = 0; u < 4; u++) {
            int i = i0 + u;
            float xna = fmaf((va[u] - smu[i]) * srs[i], gm, bt);
            float xnb = fmaf((vb[u] - smu[SCH + i]) * srs[SCH + i], gm, bt);
            float xs = xna + xnb, xd = xna - xnb;
            unsigned long long ps, pd;
            asm("mov.b64 %0, {%1, %1};" : "=l"(ps) : "f"(xs));
            asm("mov.b64 %0, {%1, %1};" : "=l"(pd) : "f"(xd));
#pragma unroll
            for (int k2 = 0; k2 < 8; k2++) {
                ulonglong2 tt = stw[i * 8 + k2];
                asm("fma.rn.f32x2 %0, %1, %2, %0;" : "+l"(acc[2*k2  ]) : "l"(ps), "l"(tt.x));
                asm("fma.rn.f32x2 %0, %1, %2, %0;" : "+l"(acc[2*k2+1]) : "l"(pd), "l"(tt.y));
            }
        }
    }
    unsigned long long* pout = (unsigned long long*)g_part + ((size_t)(ch * Bq + b) * Mq) * Dq + d;
#pragma unroll
    for (int k = 0; k < Mq; k++) pout[k * Dq] = acc[k];
}

// ---------------- reduce partials, apply complex spectral weight ----------------
__global__ void c0a_k(const float* __restrict__ wr, const float* __restrict__ wi) {
    int k = blockIdx.x, b = blockIdx.y;
    int d = blockIdx.z * 128 + threadIdx.x;
    const unsigned long long* pp = (const unsigned long long*)g_part;
    unsigned long long s = 0ull;
#pragma unroll
    for (int c = 0; c < NCH; c++) {
        unsigned long long v = pp[((size_t)(c * Bq + b) * Mq + k) * Dq + d];
        asm("add.rn.f32x2 %0, %0, %1;" : "+l"(s) : "l"(v));
    }
    float sr, si;
    asm("mov.b64 {%0, %1}, %2;" : "=f"(sr), "=f"(si) : "l"(s));
    float wrv = wr[d * Mq + k], wiv = wi[d * Mq + k];
    float Dr = sr * wrv - si * wiv;
    float Di = (k == 0) ? 0.f : fmaf(sr, wiv, si * wrv);   // irfft drops Im of bin 0
    g_D[(size_t)(b * Mq + k) * Dq + d] = make_float2(Dr, Di);
}

// ---------------- edge values xs(0), xs(S-1) ----------------
__global__ void c0b_k() {
    int b = blockIdx.x, di = threadIdx.x;
    float xsf = 0.f, xsl = 0.f;
#pragma unroll
    for (int k = 0; k < Mq; k++) {
        float2 Dv = g_D[(size_t)(b * Mq + k) * Dq + di];
        float2 t = g_tw[Mq + k];           // s=1 row: (cos w_k, -sin w_k)
        float ck = t.x, sk = -t.y;
        float m = (k == 0) ? 1.f : 2.f;
        xsf += m * Dv.x;
        xsl += m * (Dv.x * ck + Dv.y * sk);    // Re(D_k e^{-i w_k})
    }
    g_xsf[b * Dq + di] = xsf * INV_S;
    g_xsl[b * Dq + di] = xsl * INV_S;
}

// ---------------- spectral-domain conv partials: coalesced, split over di chunks ----------------
__global__ void c1_k() {
    int kg = blockIdx.x & 3, cc = blockIdx.x >> 2;
    int tile = blockIdx.y, b = blockIdx.z;
    int tid = threadIdx.x;
    int dd = tile * 128 + tid;
    int k0 = kg * 4;
    __shared__ float sDr[4][128], sDi[4][128], sxf[128], sxl[128];

    float ck[4], sk[4];
#pragma unroll
    for (int kk = 0; kk < 4; kk++) {
        float2 t = g_tw[Mq + (k0 + kk)];
        ck[kk] = t.x; sk[kk] = -t.y;
    }
#pragma unroll
    for (int kk = 0; kk < 4; kk++) {
        float2 Dv = g_D[(size_t)(b * Mq + k0 + kk) * Dq + cc * 128 + tid];
        sDr[kk][tid] = Dv.x; sDi[kk][tid] = Dv.y;
    }
    if (kg == 0) {
        sxf[tid] = g_xsf[b * Dq + cc * 128 + tid];
        sxl[tid] = g_xsl[b * Dq + cc * 128 + tid];
    }
    __syncthreads();

    float ar[4] = {0.f,0.f,0.f,0.f}, ai[4] = {0.f,0.f,0.f,0.f};
    float a0 = 0.f, aN = 0.f;
    int dibase = cc * 128;
#pragma unroll 4
    for (int j = 0; j < 128; j++) {
        size_t o = (size_t)(dibase + j) * Dq + dd;
        float w1 = g_w1[o], ws = g_ws[o], wd = g_wd[o];
#pragma unroll
        for (int kk = 0; kk < 4; kk++) {
            float hr = fmaf(ws, ck[kk], w1);
            float hi = wd * sk[kk];
            float Dr = sDr[kk][j], Di = sDi[kk][j];
            ar[kk] = fmaf(hr, Dr, ar[kk]); ar[kk] = fmaf(-hi, Di, ar[kk]);
            ai[kk] = fmaf(hr, Di, ai[kk]); ai[kk] = fmaf( hi, Dr, ai[kk]);
        }
        if (kg == 0) {
            float w0 = 0.5f * (ws - wd), w2 = 0.5f * (ws + wd);
            a0 = fmaf(-w0, sxl[j], a0);   // circular wrap removal at s=0
            aN = fmaf(-w2, sxf[j], aN);   // circular wrap removal at s=S-1
        }
    }
#pragma unroll
    for (int kk = 0; kk < 4; kk++)
        g_c1p[((size_t)(cc * Bq + b) * Mq + k0 + kk) * Dq + dd] = make_float2(ar[kk], ai[kk]);
    if (kg == 0)
        g_edg[(size_t)(cc * Bq + b) * Dq + dd] = make_float2(a0, aN);
}

// ---------------- reduce c1 partials: A_k = sc*(conv + identity), edge sums ----------------
__global__ void c1r_k() {
    int k = blockIdx.x, b = blockIdx.y, d = threadIdx.x;
    float sr = 0.f, si = 0.f;
#pragma unroll
    for (int cc = 0; cc < 4; cc++) {
        float2 v = g_c1p[((size_t)(cc * Bq + b) * Mq + k) * Dq + d];
        sr += v.x; si += v.y;
    }
    float2 Dv = g_D[(size_t)(b * Mq + k) * Dq + d];
    float sc = (k == 0) ? INV_S : 2.f * INV_S;
    g_A[(size_t)(b * Mq + k) * Dq + d] = make_float2(sc * (sr + Dv.x), sc * (si + Dv.y));
    if (k == 0) {
        float e0 = 0.f, eN = 0.f;
#pragma unroll
        for (int cc = 0; cc < 4; cc++) {
            float2 e = g_edg[(size_t)(cc * Bq + b) * Dq + d];
            e0 += e.x; eN += e.y;
        }
        g_c0[b * Dq + d] = e0;
        g_cN[b * Dq + d] = eN;
    }
}

// ---------------- final with half-period pairing ----------------
// out(s)      = x(s)      + cb + (pe + po)
// out(s+2048) = x(s+2048) + cb + (pe - po)
// grid (NCH, Bq, 2 d-tiles), block 256
__global__ void __launch_bounds__(256) final_k(const float* __restrict__ x, const float* __restrict__ cb,
                        float* __restrict__ out) {
    __shared__ ulonglong2 stw[SCH * Mq / 2];
    int b = blockIdx.y, ch = blockIdx.x;
    int d = blockIdx.z * 256 + threadIdx.x;
    int t = threadIdx.x;
    int s0 = ch * SCH;
    const ulonglong2* twp = (const ulonglong2*)(g_tw + (size_t)s0 * Mq);
#pragma unroll
    for (int i = t; i < SCH * Mq / 2; i += 256) stw[i] = twp[i];
    __syncthreads();

    unsigned long long a[Mq];
    const unsigned long long* Ap = (const unsigned long long*)g_A + (size_t)b * Mq * Dq + d;
#pragma unroll
    for (int k = 0; k < Mq; k++) a[k] = Ap[k * Dq];

    float base_add = cb[d];
    float c0v = g_c0[b * Dq + d], cNv = g_cN[b * Dq + d];
    const float* xa = x   + ((size_t)(b * Sq + s0)) * Dq + d;
    const float* xb = xa + (size_t)Hq * Dq;
    float*       oa = out + ((size_t)(b * Sq + s0)) * Dq + d;
    float*       ob = oa + (size_t)Hq * Dq;

    for (int i0 = 0; i0 < SCH; i0 += 4) {
        float va[4], vb[4];
#pragma unroll
        for (int u = 0; u < 4; u++) { va[u] = xa[(i0 + u) * Dq]; vb[u] = xb[(i0 + u) * Dq]; }
#pragma unroll
        for (int u = 0; u < 4; u++) {
            int i = i0 + u;
            unsigned long long ae = 0ull, ao = 0ull;
#pragma unroll
            for (int k2 = 0; k2 < 8; k2++) {
                ulonglong2 tt = stw[i * 8 + k2];
                asm("fma.rn.f32x2 %0, %1, %2, %0;" : "+l"(ae) : "l"(a[2*k2  ]), "l"(tt.x));
                asm("fma.rn.f32x2 %0, %1, %2, %0;" : "+l"(ao) : "l"(a[2*k2+1]), "l"(tt.y));
            }
            float ex, ey, ox, oy;
            asm("mov.b64 {%0, %1}, %2;" : "=f"(ex), "=f"(ey) : "l"(ae));
            asm("mov.b64 {%0, %1}, %2;" : "=f"(ox), "=f"(oy) : "l"(ao));
            float pe = ex + ey, po = ox + oy;
            float vlo = va[u] + base_add + (pe + po);
            float vhi = vb[u] + base_add + (pe - po);
            int s = s0 + i;
            if (s == 0)      vlo += c0v;   // s = 0
            if (s == Hq - 1) vhi += cNv;   // s+2048 = 4095
            oa[i * Dq] = vlo;
            ob[i * Dq] = vhi;
        }
    }
}

// ---------------- launch ----------------
extern "C" void kernel_launch(void* const* d_in, const int* in_sizes, int n_in,
                              void* d_out, int out_size) {
    (void)in_sizes; (void)n_in; (void)out_size;
    const float* x     = (const float*)d_in[0];
    const float* gamma = (const float*)d_in[1];
    const float* beta  = (const float*)d_in[2];
    const float* wr    = (const float*)d_in[3];
    const float* wi    = (const float*)d_in[4];
    const float* cw    = (const float*)d_in[5];
    const float* cb    = (const float*)d_in[6];
    float* out = (float*)d_out;

    twiddle_k<<<(Hq * Mq) / 256, 256>>>();
    tr_k<<<dim3(Dq / 32, Dq / 32), dim3(32, 8)>>>(cw);
    ln_k<<<(Bq * Sq) / 8, 256>>>(x);
    proj_k<<<dim3(NCH, Bq, 2), 256>>>(x, gamma, beta);
    c0a_k<<<dim3(Mq, Bq, 4), 128>>>(wr, wi);
    c0b_k<<<Bq, Dq>>>();
    c1_k<<<dim3(16, 4, Bq), 128>>>();
    c1r_k<<<dim3(Mq, Bq), Dq>>>();
    final_k<<<dim3(NCH, Bq, 2), 256>>>(x, cb, out);
}

// round 6
// speedup vs baseline: 2.9854x; 1.0784x over previous
#include <cuda_runtime.h>

#define Bq 8
#define Sq 4096
#define Hq 2048               // half period
#define Dq 512
#define Mq 16
#define NCH 32
#define SCH (Hq/NCH)          // 64 s_lo rows per chunk
#define INV_S (1.0f/4096.0f)

// ---------------- device scratch (no allocations allowed) ----------------
__device__ __align__(16) float2 g_tw[Hq*Mq];   // per (s,k), s<2048: (cos(w_k s), -sin(w_k s))
__device__ float  g_mu[Bq*Sq];
__device__ float  g_rs[Bq*Sq];
__device__ float2 g_part[NCH*Bq*Mq*Dq];        // partial projections [chunk][b][k][d] (re,im)
__device__ float2 g_D[Bq*Mq*Dq];               // spectral coeffs with w applied [b][k][d]
__device__ float  g_xsf[Bq*Dq];                // xs at s=0   (scaled by 1/S)
__device__ float  g_xsl[Bq*Dq];                // xs at s=S-1 (scaled by 1/S)
__device__ float2 g_A[Bq*Mq*Dq];               // combined scaled coeffs [b][k][d]
__device__ float  g_c0[Bq*Dq];                 // boundary correction at s=0
__device__ float  g_cN[Bq*Dq];                 // boundary correction at s=S-1
// transposed conv weights, [di][dd] layout (coalesced along dd)
__device__ float  g_w1[Dq*Dq];
__device__ float  g_ws[Dq*Dq];                 // w0+w2
__device__ float  g_wd[Dq*Dq];                 // w2-w0
// c1 partials over di-chunks
__device__ float2 g_c1p[4*Bq*Mq*Dq];           // [cc][b][k][dd]
__device__ float2 g_edg[4*Bq*Dq];              // [cc][b][dd] -> (a0, aN)

// ---------------- twiddle table (float sincospi: exact argument) ----------------
__global__ void twiddle_k() {
    int i = blockIdx.x * 256 + threadIdx.x;   // i = s*16 + k, s < 2048
    int s = i >> 4, k = i & 15;
    int ks = (k * s) & (Sq - 1);
    float sf, cf;
    sincospif((float)ks * (1.0f / 2048.0f), &sf, &cf);
    g_tw[i] = make_float2(cf, -sf);
}

// ---------------- transpose conv weights into [di][dd] planes ----------------
__global__ void tr_k(const float* __restrict__ cw) {
    __shared__ float t1[32][33], ts[32][33], td[32][33];
    int di0 = blockIdx.x * 32, dd0 = blockIdx.y * 32;
    int tx = threadIdx.x, ty = threadIdx.y;   // block (32,8)
#pragma unroll
    for (int jj = 0; jj < 4; jj++) {
        int ddl = ty + jj * 8;
        const float* p = cw + ((size_t)(dd0 + ddl) * Dq + di0 + tx) * 3;
        float w0 = p[0], w1 = p[1], w2 = p[2];
        t1[ddl][tx] = w1;
        ts[ddl][tx] = w0 + w2;
        td[ddl][tx] = w2 - w0;
    }
    __syncthreads();
#pragma unroll
    for (int jj = 0; jj < 4; jj++) {
        int dil = ty + jj * 8;
        size_t o = (size_t)(di0 + dil) * Dq + dd0 + tx;
        g_w1[o] = t1[tx][dil];
        g_ws[o] = ts[tx][dil];
        g_wd[o] = td[tx][dil];
    }
}

// ---------------- LayerNorm stats: one warp per (b,s) row ----------------
__global__ void ln_k(const float* __restrict__ x) {
    int lane = threadIdx.x & 31;
    int row  = blockIdx.x * 8 + (threadIdx.x >> 5);   // b*Sq + s
    const float4* xr = (const float4*)(x + (size_t)row * Dq);
    float s1 = 0.f, s2 = 0.f;
#pragma unroll
    for (int it = 0; it < 4; it++) {
        float4 v = xr[lane + it * 32];
        s1 += (v.x + v.y) + (v.z + v.w);
        s2 = fmaf(v.x, v.x, s2); s2 = fmaf(v.y, v.y, s2);
        s2 = fmaf(v.z, v.z, s2); s2 = fmaf(v.w, v.w, s2);
    }
#pragma unroll
    for (int off = 16; off > 0; off >>= 1) {
        s1 += __shfl_xor_sync(0xffffffffu, s1, off);
        s2 += __shfl_xor_sync(0xffffffffu, s2, off);
    }
    if (lane == 0) {
        float mu  = s1 * (1.f / Dq);
        float var = fmaf(-mu, mu, s2 * (1.f / Dq));
        g_mu[row] = mu;
        g_rs[row] = rsqrtf(var + 1e-5f);
    }
}

// ---------------- projection with half-period pairing + prefetch pipeline ----------------
// pair (s, s+2048): P_k += (xn_a + (-1)^k xn_b) * e^{-i w_k s}
// grid (NCH, Bq, 2 d-tiles), block 256
__global__ void proj_k(const float* __restrict__ x,
                       const float* __restrict__ gamma,
                       const float* __restrict__ beta) {
    __shared__ ulonglong2 stw[SCH * Mq / 2];   // 8 KB
    __shared__ float smu[2 * SCH], srs[2 * SCH];
    int b = blockIdx.y, ch = blockIdx.x;
    int d = blockIdx.z * 256 + threadIdx.x;
    int t = threadIdx.x;
    int s0 = ch * SCH;
    const ulonglong2* twp = (const ulonglong2*)(g_tw + (size_t)s0 * Mq);
#pragma unroll
    for (int i = t; i < SCH * Mq / 2; i += 256) stw[i] = twp[i];
    int row0 = b * Sq + s0;
    if (t < SCH)            { smu[t] = g_mu[row0 + t];              srs[t] = g_rs[row0 + t]; }
    else if (t < 2 * SCH)   { smu[t] = g_mu[row0 + Hq + (t - SCH)]; srs[t] = g_rs[row0 + Hq + (t - SCH)]; }
    __syncthreads();

    float gm = gamma[d], bt = beta[d];
    unsigned long long acc[Mq];
#pragma unroll
    for (int k = 0; k < Mq; k++) acc[k] = 0ull;

    const float* xa = x + ((size_t)row0) * Dq + d;
    const float* xb = xa + (size_t)Hq * Dq;

    float va[4], vb[4];
#pragma unroll
    for (int u = 0; u < 4; u++) { va[u] = xa[u * Dq]; vb[u] = xb[u * Dq]; }

#pragma unroll 1
    for (int i0 = 0; i0 < SCH; i0 += 4) {
        int ip = (i0 + 4 < SCH) ? (i0 + 4) : (SCH - 4);   // clamped prefetch
        float na[4], nb[4];
#pragma unroll
        for (int u = 0; u < 4; u++) { na[u] = xa[(ip + u) * Dq]; nb[u] = xb[(ip + u) * Dq]; }
#pragma unroll
        for (int u = 0; u < 4; u++) {
            int i = i0 + u;
            float xna = fmaf((va[u] - smu[i]) * srs[i], gm, bt);
            float xnb = fmaf((vb[u] - smu[SCH + i]) * srs[SCH + i], gm, bt);
            float xs = xna + xnb, xd = xna - xnb;
            unsigned long long ps, pd;
            asm("mov.b64 %0, {%1, %1};" : "=l"(ps) : "f"(xs));
            asm("mov.b64 %0, {%1, %1};" : "=l"(pd) : "f"(xd));
#pragma unroll
            for (int k2 = 0; k2 < 8; k2++) {
                ulonglong2 tt = stw[i * 8 + k2];
                asm("fma.rn.f32x2 %0, %1, %2, %0;" : "+l"(acc[2*k2  ]) : "l"(ps), "l"(tt.x));
                asm("fma.rn.f32x2 %0, %1, %2, %0;" : "+l"(acc[2*k2+1]) : "l"(pd), "l"(tt.y));
            }
        }
#pragma unroll
        for (int u = 0; u < 4; u++) { va[u] = na[u]; vb[u] = nb[u]; }
    }
    unsigned long long* pout = (unsigned long long*)g_part + ((size_t)(ch * Bq + b) * Mq) * Dq + d;
#pragma unroll
    for (int k = 0; k < Mq; k++) pout[k * Dq] = acc[k];
}

// ---------------- reduce partials, apply complex spectral weight ----------------
__global__ void c0a_k(const float* __restrict__ wr, const float* __restrict__ wi) {
    int k = blockIdx.x, b = blockIdx.y;
    int d = blockIdx.z * 128 + threadIdx.x;
    const unsigned long long* pp = (const unsigned long long*)g_part;
    unsigned long long s = 0ull;
#pragma unroll
    for (int c = 0; c < NCH; c++) {
        unsigned long long v = pp[((size_t)(c * Bq + b) * Mq + k) * Dq + d];
        asm("add.rn.f32x2 %0, %0, %1;" : "+l"(s) : "l"(v));
    }
    float sr, si;
    asm("mov.b64 {%0, %1}, %2;" : "=f"(sr), "=f"(si) : "l"(s));
    float wrv = wr[d * Mq + k], wiv = wi[d * Mq + k];
    float Dr = sr * wrv - si * wiv;
    float Di = (k == 0) ? 0.f : fmaf(sr, wiv, si * wrv);   // irfft drops Im of bin 0
    g_D[(size_t)(b * Mq + k) * Dq + d] = make_float2(Dr, Di);
}

// ---------------- edge values xs(0), xs(S-1) ----------------
__global__ void c0b_k() {
    int b = blockIdx.x, di = threadIdx.x;
    float xsf = 0.f, xsl = 0.f;
#pragma unroll
    for (int k = 0; k < Mq; k++) {
        float2 Dv = g_D[(size_t)(b * Mq + k) * Dq + di];
        float2 t = g_tw[Mq + k];           // s=1 row: (cos w_k, -sin w_k)
        float ck = t.x, sk = -t.y;
        float m = (k == 0) ? 1.f : 2.f;
        xsf += m * Dv.x;
        xsl += m * (Dv.x * ck + Dv.y * sk);    // Re(D_k e^{-i w_k})
    }
    g_xsf[b * Dq + di] = xsf * INV_S;
    g_xsl[b * Dq + di] = xsl * INV_S;
}

// ---------------- spectral-domain conv partials: coalesced, split over di chunks ----------------
__global__ void c1_k() {
    int kg = blockIdx.x & 3, cc = blockIdx.x >> 2;
    int tile = blockIdx.y, b = blockIdx.z;
    int tid = threadIdx.x;
    int dd = tile * 128 + tid;
    int k0 = kg * 4;
    __shared__ float sDr[4][128], sDi[4][128], sxf[128], sxl[128];

    float ck[4], sk[4];
#pragma unroll
    for (int kk = 0; kk < 4; kk++) {
        float2 t = g_tw[Mq + (k0 + kk)];
        ck[kk] = t.x; sk[kk] = -t.y;
    }
#pragma unroll
    for (int kk = 0; kk < 4; kk++) {
        float2 Dv = g_D[(size_t)(b * Mq + k0 + kk) * Dq + cc * 128 + tid];
        sDr[kk][tid] = Dv.x; sDi[kk][tid] = Dv.y;
    }
    if (kg == 0) {
        sxf[tid] = g_xsf[b * Dq + cc * 128 + tid];
        sxl[tid] = g_xsl[b * Dq + cc * 128 + tid];
    }
    __syncthreads();

    float ar[4] = {0.f,0.f,0.f,0.f}, ai[4] = {0.f,0.f,0.f,0.f};
    float a0 = 0.f, aN = 0.f;
    int dibase = cc * 128;
#pragma unroll 4
    for (int j = 0; j < 128; j++) {
        size_t o = (size_t)(dibase + j) * Dq + dd;
        float w1 = g_w1[o], ws = g_ws[o], wd = g_wd[o];
#pragma unroll
        for (int kk = 0; kk < 4; kk++) {
            float hr = fmaf(ws, ck[kk], w1);
            float hi = wd * sk[kk];
            float Dr = sDr[kk][j], Di = sDi[kk][j];
            ar[kk] = fmaf(hr, Dr, ar[kk]); ar[kk] = fmaf(-hi, Di, ar[kk]);
            ai[kk] = fmaf(hr, Di, ai[kk]); ai[kk] = fmaf( hi, Dr, ai[kk]);
        }
        if (kg == 0) {
            float w0 = 0.5f * (ws - wd), w2 = 0.5f * (ws + wd);
            a0 = fmaf(-w0, sxl[j], a0);   // circular wrap removal at s=0
            aN = fmaf(-w2, sxf[j], aN);   // circular wrap removal at s=S-1
        }
    }
#pragma unroll
    for (int kk = 0; kk < 4; kk++)
        g_c1p[((size_t)(cc * Bq + b) * Mq + k0 + kk) * Dq + dd] = make_float2(ar[kk], ai[kk]);
    if (kg == 0)
        g_edg[(size_t)(cc * Bq + b) * Dq + dd] = make_float2(a0, aN);
}

// ---------------- reduce c1 partials: A_k = sc*(conv + identity), edge sums ----------------
__global__ void c1r_k() {
    int k = blockIdx.x, b = blockIdx.y, d = threadIdx.x;
    float sr = 0.f, si = 0.f;
#pragma unroll
    for (int cc = 0; cc < 4; cc++) {
        float2 v = g_c1p[((size_t)(cc * Bq + b) * Mq + k) * Dq + d];
        sr += v.x; si += v.y;
    }
    float2 Dv = g_D[(size_t)(b * Mq + k) * Dq + d];
    float sc = (k == 0) ? INV_S : 2.f * INV_S;
    g_A[(size_t)(b * Mq + k) * Dq + d] = make_float2(sc * (sr + Dv.x), sc * (si + Dv.y));
    if (k == 0) {
        float e0 = 0.f, eN = 0.f;
#pragma unroll
        for (int cc = 0; cc < 4; cc++) {
            float2 e = g_edg[(size_t)(cc * Bq + b) * Dq + d];
            e0 += e.x; eN += e.y;
        }
        g_c0[b * Dq + d] = e0;
        g_cN[b * Dq + d] = eN;
    }
}

// ---------------- final with half-period pairing + prefetch pipeline ----------------
// out(s)      = x(s)      + cb + (pe + po)
// out(s+2048) = x(s+2048) + cb + (pe - po)
// grid (NCH, Bq, 2 d-tiles), block 256
__global__ void final_k(const float* __restrict__ x, const float* __restrict__ cb,
                        float* __restrict__ out) {
    __shared__ ulonglong2 stw[SCH * Mq / 2];
    int b = blockIdx.y, ch = blockIdx.x;
    int d = blockIdx.z * 256 + threadIdx.x;
    int t = threadIdx.x;
    int s0 = ch * SCH;
    const ulonglong2* twp = (const ulonglong2*)(g_tw + (size_t)s0 * Mq);
#pragma unroll
    for (int i = t; i < SCH * Mq / 2; i += 256) stw[i] = twp[i];
    __syncthreads();

    unsigned long long a[Mq];
    const unsigned long long* Ap = (const unsigned long long*)g_A + (size_t)b * Mq * Dq + d;
#pragma unroll
    for (int k = 0; k < Mq; k++) a[k] = Ap[k * Dq];

    float base_add = cb[d];
    float c0v = g_c0[b * Dq + d], cNv = g_cN[b * Dq + d];
    const float* xa = x   + ((size_t)(b * Sq + s0)) * Dq + d;
    const float* xb = xa + (size_t)Hq * Dq;
    float*       oa = out + ((size_t)(b * Sq + s0)) * Dq + d;
    float*       ob = oa + (size_t)Hq * Dq;

    float va[4], vb[4];
#pragma unroll
    for (int u = 0; u < 4; u++) { va[u] = xa[u * Dq]; vb[u] = xb[u * Dq]; }

#pragma unroll 1
    for (int i0 = 0; i0 < SCH; i0 += 4) {
        int ip = (i0 + 4 < SCH) ? (i0 + 4) : (SCH - 4);   // clamped prefetch
        float na[4], nb[4];
#pragma unroll
        for (int u = 0; u < 4; u++) { na[u] = xa[(ip + u) * Dq]; nb[u] = xb[(ip + u) * Dq]; }
#pragma unroll
        for (int u = 0; u < 4; u++) {
            int i = i0 + u;
            unsigned long long ae = 0ull, ao = 0ull;
#pragma unroll
            for (int k2 = 0; k2 < 8; k2++) {
                ulonglong2 tt = stw[i * 8 + k2];
                asm("fma.rn.f32x2 %0, %1, %2, %0;" : "+l"(ae) : "l"(a[2*k2  ]), "l"(tt.x));
                asm("fma.rn.f32x2 %0, %1, %2, %0;" : "+l"(ao) : "l"(a[2*k2+1]), "l"(tt.y));
            }
            float ex, ey, ox, oy;
            asm("mov.b64 {%0, %1}, %2;" : "=f"(ex), "=f"(ey) : "l"(ae));
            asm("mov.b64 {%0, %1}, %2;" : "=f"(ox), "=f"(oy) : "l"(ao));
            float pe = ex + ey, po = ox + oy;
            float vlo = va[u] + base_add + (pe + po);
            float vhi = vb[u] + base_add + (pe - po);
            int s = s0 + i;
            if (s == 0)      vlo += c0v;   // s = 0
            if (s == Hq - 1) vhi += cNv;   // s+2048 = 4095
            oa[i * Dq] = vlo;
            ob[i * Dq] = vhi;
        }
#pragma unroll
        for (int u = 0; u < 4; u++) { va[u] = na[u]; vb[u] = nb[u]; }
    }
}

// ---------------- launch ----------------
extern "C" void kernel_launch(void* const* d_in, const int* in_sizes, int n_in,
                              void* d_out, int out_size) {
    (void)in_sizes; (void)n_in; (void)out_size;
    const float* x     = (const float*)d_in[0];
    const float* gamma = (const float*)d_in[1];
    const float* beta  = (const float*)d_in[2];
    const float* wr    = (const float*)d_in[3];
    const float* wi    = (const float*)d_in[4];
    const float* cw    = (const float*)d_in[5];
    const float* cb    = (const float*)d_in[6];
    float* out = (float*)d_out;

    twiddle_k<<<(Hq * Mq) / 256, 256>>>();
    tr_k<<<dim3(Dq / 32, Dq / 32), dim3(32, 8)>>>(cw);
    ln_k<<<(Bq * Sq) / 8, 256>>>(x);
    proj_k<<<dim3(NCH, Bq, 2), 256>>>(x, gamma, beta);
    c0a_k<<<dim3(Mq, Bq, 4), 128>>>(wr, wi);
    c0b_k<<<Bq, Dq>>>();
    c1_k<<<dim3(16, 4, Bq), 128>>>();
    c1r_k<<<dim3(Mq, Bq), Dq>>>();
    final_k<<<dim3(NCH, Bq, 2), 256>>>(x, cb, out);
}

// round 7
// speedup vs baseline: 3.1194x; 1.0449x over previous
#include <cuda_runtime.h>

#define Bq 8
#define Sq 4096
#define Hq 2048               // half period
#define Dq 512
#define Mq 16
#define NCH 32
#define SCH (Hq/NCH)          // 64 s_lo rows per chunk
#define INV_S (1.0f/4096.0f)

// ---------------- device scratch (no allocations allowed) ----------------
__device__ __align__(16) float2 g_tw[Hq*Mq];   // per (s,k), s<2048: (cos(w_k s), -sin(w_k s))
__device__ float  g_mu[Bq*Sq];
__device__ float  g_rs[Bq*Sq];
__device__ float2 g_part[NCH*Bq*Mq*Dq];        // partial projections [chunk][b][k][d] (re,im)
__device__ float2 g_D[Bq*Mq*Dq];               // spectral coeffs with w applied [b][k][d]
__device__ float  g_xsf[Bq*Dq];                // xs at s=0   (scaled by 1/S)
__device__ float  g_xsl[Bq*Dq];                // xs at s=S-1 (scaled by 1/S)
__device__ float2 g_A[Bq*Mq*Dq];               // combined scaled coeffs [b][k][d]
__device__ float  g_c0[Bq*Dq];                 // boundary correction at s=0
__device__ float  g_cN[Bq*Dq];                 // boundary correction at s=S-1
// transposed conv weights, [di][dd] layout (coalesced along dd)
__device__ float  g_w1[Dq*Dq];
__device__ float  g_ws[Dq*Dq];                 // w0+w2
__device__ float  g_wd[Dq*Dq];                 // w2-w0
// c1 partials over di-chunks
__device__ float2 g_c1p[4*Bq*Mq*Dq];           // [cc][b][k][dd]
__device__ float2 g_edg[4*Bq*Dq];              // [cc][b][dd] -> (a0, aN)

// ---------------- twiddle table (float sincospi: exact argument) ----------------
__global__ void twiddle_k() {
    int i = blockIdx.x * 256 + threadIdx.x;   // i = s*16 + k, s < 2048
    int s = i >> 4, k = i & 15;
    int ks = (k * s) & (Sq - 1);
    float sf, cf;
    sincospif((float)ks * (1.0f / 2048.0f), &sf, &cf);
    g_tw[i] = make_float2(cf, -sf);
}

// ---------------- transpose conv weights into [di][dd] planes ----------------
__global__ void tr_k(const float* __restrict__ cw) {
    __shared__ float t1[32][33], ts[32][33], td[32][33];
    int di0 = blockIdx.x * 32, dd0 = blockIdx.y * 32;
    int tx = threadIdx.x, ty = threadIdx.y;   // block (32,8)
#pragma unroll
    for (int jj = 0; jj < 4; jj++) {
        int ddl = ty + jj * 8;
        const float* p = cw + ((size_t)(dd0 + ddl) * Dq + di0 + tx) * 3;
        float w0 = p[0], w1 = p[1], w2 = p[2];
        t1[ddl][tx] = w1;
        ts[ddl][tx] = w0 + w2;
        td[ddl][tx] = w2 - w0;
    }
    __syncthreads();
#pragma unroll
    for (int jj = 0; jj < 4; jj++) {
        int dil = ty + jj * 8;
        size_t o = (size_t)(di0 + dil) * Dq + dd0 + tx;
        g_w1[o] = t1[tx][dil];
        g_ws[o] = ts[tx][dil];
        g_wd[o] = td[tx][dil];
    }
}

// ---------------- LayerNorm stats: one warp per (b,s) row ----------------
__global__ void ln_k(const float* __restrict__ x) {
    int lane = threadIdx.x & 31;
    int row  = blockIdx.x * 8 + (threadIdx.x >> 5);   // b*Sq + s
    const float4* xr = (const float4*)(x + (size_t)row * Dq);
    float s1 = 0.f, s2 = 0.f;
#pragma unroll
    for (int it = 0; it < 4; it++) {
        float4 v = xr[lane + it * 32];
        s1 += (v.x + v.y) + (v.z + v.w);
        s2 = fmaf(v.x, v.x, s2); s2 = fmaf(v.y, v.y, s2);
        s2 = fmaf(v.z, v.z, s2); s2 = fmaf(v.w, v.w, s2);
    }
#pragma unroll
    for (int off = 16; off > 0; off >>= 1) {
        s1 += __shfl_xor_sync(0xffffffffu, s1, off);
        s2 += __shfl_xor_sync(0xffffffffu, s2, off);
    }
    if (lane == 0) {
        float mu  = s1 * (1.f / Dq);
        float var = fmaf(-mu, mu, s2 * (1.f / Dq));
        g_mu[row] = mu;
        g_rs[row] = rsqrtf(var + 1e-5f);
    }
}

// ---------------- projection with half-period pairing + depth-8 prefetch pipeline ----------------
// pair (s, s+2048): P_k += (xn_a + (-1)^k xn_b) * e^{-i w_k s}
// grid (NCH, Bq, 2 d-tiles), block 256
__global__ void proj_k(const float* __restrict__ x,
                       const float* __restrict__ gamma,
                       const float* __restrict__ beta) {
    __shared__ ulonglong2 stw[SCH * Mq / 2];   // 8 KB
    __shared__ float smu[2 * SCH], srs[2 * SCH];
    int b = blockIdx.y, ch = blockIdx.x;
    int d = blockIdx.z * 256 + threadIdx.x;
    int t = threadIdx.x;
    int s0 = ch * SCH;
    const ulonglong2* twp = (const ulonglong2*)(g_tw + (size_t)s0 * Mq);
#pragma unroll
    for (int i = t; i < SCH * Mq / 2; i += 256) stw[i] = twp[i];
    int row0 = b * Sq + s0;
    if (t < SCH)            { smu[t] = g_mu[row0 + t];              srs[t] = g_rs[row0 + t]; }
    else if (t < 2 * SCH)   { smu[t] = g_mu[row0 + Hq + (t - SCH)]; srs[t] = g_rs[row0 + Hq + (t - SCH)]; }
    __syncthreads();

    float gm = gamma[d], bt = beta[d];
    unsigned long long acc[Mq];
#pragma unroll
    for (int k = 0; k < Mq; k++) acc[k] = 0ull;

    const float* xa = x + ((size_t)row0) * Dq + d;
    const float* xb = xa + (size_t)Hq * Dq;

    float va[8], vb[8];
#pragma unroll
    for (int u = 0; u < 8; u++) { va[u] = xa[u * Dq]; vb[u] = xb[u * Dq]; }

#pragma unroll 1
    for (int i0 = 0; i0 < SCH; i0 += 8) {
        int ip = (i0 + 8 < SCH) ? (i0 + 8) : (SCH - 8);   // clamped prefetch
        float na[8], nb[8];
#pragma unroll
        for (int u = 0; u < 8; u++) { na[u] = xa[(ip + u) * Dq]; nb[u] = xb[(ip + u) * Dq]; }
#pragma unroll
        for (int u = 0; u < 8; u++) {
            int i = i0 + u;
            float xna = fmaf((va[u] - smu[i]) * srs[i], gm, bt);
            float xnb = fmaf((vb[u] - smu[SCH + i]) * srs[SCH + i], gm, bt);
            float xs = xna + xnb, xd = xna - xnb;
            unsigned long long ps, pd;
            asm("mov.b64 %0, {%1, %1};" : "=l"(ps) : "f"(xs));
            asm("mov.b64 %0, {%1, %1};" : "=l"(pd) : "f"(xd));
#pragma unroll
            for (int k2 = 0; k2 < 8; k2++) {
                ulonglong2 tt = stw[i * 8 + k2];
                asm("fma.rn.f32x2 %0, %1, %2, %0;" : "+l"(acc[2*k2  ]) : "l"(ps), "l"(tt.x));
                asm("fma.rn.f32x2 %0, %1, %2, %0;" : "+l"(acc[2*k2+1]) : "l"(pd), "l"(tt.y));
            }
        }
#pragma unroll
        for (int u = 0; u < 8; u++) { va[u] = na[u]; vb[u] = nb[u]; }
    }
    unsigned long long* pout = (unsigned long long*)g_part + ((size_t)(ch * Bq + b) * Mq) * Dq + d;
#pragma unroll
    for (int k = 0; k < Mq; k++) pout[k * Dq] = acc[k];
}

// ---------------- reduce partials, apply complex spectral weight ----------------
__global__ void c0a_k(const float* __restrict__ wr, const float* __restrict__ wi) {
    int k = blockIdx.x, b = blockIdx.y;
    int d = blockIdx.z * 128 + threadIdx.x;
    const unsigned long long* pp = (const unsigned long long*)g_part;
    unsigned long long s = 0ull;
#pragma unroll
    for (int c = 0; c < NCH; c++) {
        unsigned long long v = pp[((size_t)(c * Bq + b) * Mq + k) * Dq + d];
        asm("add.rn.f32x2 %0, %0, %1;" : "+l"(s) : "l"(v));
    }
    float sr, si;
    asm("mov.b64 {%0, %1}, %2;" : "=f"(sr), "=f"(si) : "l"(s));
    float wrv = wr[d * Mq + k], wiv = wi[d * Mq + k];
    float Dr = sr * wrv - si * wiv;
    float Di = (k == 0) ? 0.f : fmaf(sr, wiv, si * wrv);   // irfft drops Im of bin 0
    g_D[(size_t)(b * Mq + k) * Dq + d] = make_float2(Dr, Di);
}

// ---------------- edge values xs(0), xs(S-1) ----------------
__global__ void c0b_k() {
    int b = blockIdx.x, di = threadIdx.x;
    float xsf = 0.f, xsl = 0.f;
#pragma unroll
    for (int k = 0; k < Mq; k++) {
        float2 Dv = g_D[(size_t)(b * Mq + k) * Dq + di];
        float2 t = g_tw[Mq + k];           // s=1 row: (cos w_k, -sin w_k)
        float ck = t.x, sk = -t.y;
        float m = (k == 0) ? 1.f : 2.f;
        xsf += m * Dv.x;
        xsl += m * (Dv.x * ck + Dv.y * sk);    // Re(D_k e^{-i w_k})
    }
    g_xsf[b * Dq + di] = xsf * INV_S;
    g_xsl[b * Dq + di] = xsl * INV_S;
}

// ---------------- spectral-domain conv partials: coalesced, split over di chunks ----------------
__global__ void c1_k() {
    int kg = blockIdx.x & 3, cc = blockIdx.x >> 2;
    int tile = blockIdx.y, b = blockIdx.z;
    int tid = threadIdx.x;
    int dd = tile * 128 + tid;
    int k0 = kg * 4;
    __shared__ float sDr[4][128], sDi[4][128], sxf[128], sxl[128];

    float ck[4], sk[4];
#pragma unroll
    for (int kk = 0; kk < 4; kk++) {
        float2 t = g_tw[Mq + (k0 + kk)];
        ck[kk] = t.x; sk[kk] = -t.y;
    }
#pragma unroll
    for (int kk = 0; kk < 4; kk++) {
        float2 Dv = g_D[(size_t)(b * Mq + k0 + kk) * Dq + cc * 128 + tid];
        sDr[kk][tid] = Dv.x; sDi[kk][tid] = Dv.y;
    }
    if (kg == 0) {
        sxf[tid] = g_xsf[b * Dq + cc * 128 + tid];
        sxl[tid] = g_xsl[b * Dq + cc * 128 + tid];
    }
    __syncthreads();

    float ar[4] = {0.f,0.f,0.f,0.f}, ai[4] = {0.f,0.f,0.f,0.f};
    float a0 = 0.f, aN = 0.f;
    int dibase = cc * 128;
#pragma unroll 4
    for (int j = 0; j < 128; j++) {
        size_t o = (size_t)(dibase + j) * Dq + dd;
        float w1 = g_w1[o], ws = g_ws[o], wd = g_wd[o];
#pragma unroll
        for (int kk = 0; kk < 4; kk++) {
            float hr = fmaf(ws, ck[kk], w1);
            float hi = wd * sk[kk];
            float Dr = sDr[kk][j], Di = sDi[kk][j];
            ar[kk] = fmaf(hr, Dr, ar[kk]); ar[kk] = fmaf(-hi, Di, ar[kk]);
            ai[kk] = fmaf(hr, Di, ai[kk]); ai[kk] = fmaf( hi, Dr, ai[kk]);
        }
        if (kg == 0) {
            float w0 = 0.5f * (ws - wd), w2 = 0.5f * (ws + wd);
            a0 = fmaf(-w0, sxl[j], a0);   // circular wrap removal at s=0
            aN = fmaf(-w2, sxf[j], aN);   // circular wrap removal at s=S-1
        }
    }
#pragma unroll
    for (int kk = 0; kk < 4; kk++)
        g_c1p[((size_t)(cc * Bq + b) * Mq + k0 + kk) * Dq + dd] = make_float2(ar[kk], ai[kk]);
    if (kg == 0)
        g_edg[(size_t)(cc * Bq + b) * Dq + dd] = make_float2(a0, aN);
}

// ---------------- reduce c1 partials: A_k = sc*(conv + identity), edge sums ----------------
__global__ void c1r_k() {
    int k = blockIdx.x, b = blockIdx.y, d = threadIdx.x;
    float sr = 0.f, si = 0.f;
#pragma unroll
    for (int cc = 0; cc < 4; cc++) {
        float2 v = g_c1p[((size_t)(cc * Bq + b) * Mq + k) * Dq + d];
        sr += v.x; si += v.y;
    }
    float2 Dv = g_D[(size_t)(b * Mq + k) * Dq + d];
    float sc = (k == 0) ? INV_S : 2.f * INV_S;
    g_A[(size_t)(b * Mq + k) * Dq + d] = make_float2(sc * (sr + Dv.x), sc * (si + Dv.y));
    if (k == 0) {
        float e0 = 0.f, eN = 0.f;
#pragma unroll
        for (int cc = 0; cc < 4; cc++) {
            float2 e = g_edg[(size_t)(cc * Bq + b) * Dq + d];
            e0 += e.x; eN += e.y;
        }
        g_c0[b * Dq + d] = e0;
        g_cN[b * Dq + d] = eN;
    }
}

// ---------------- final with half-period pairing + depth-8 prefetch pipeline ----------------
// out(s)      = x(s)      + cb + (pe + po)
// out(s+2048) = x(s+2048) + cb + (pe - po)
// grid (NCH, Bq, 2 d-tiles), block 256
__global__ void final_k(const float* __restrict__ x, const float* __restrict__ cb,
                        float* __restrict__ out) {
    __shared__ ulonglong2 stw[SCH * Mq / 2];
    int b = blockIdx.y, ch = blockIdx.x;
    int d = blockIdx.z * 256 + threadIdx.x;
    int t = threadIdx.x;
    int s0 = ch * SCH;
    const ulonglong2* twp = (const ulonglong2*)(g_tw + (size_t)s0 * Mq);
#pragma unroll
    for (int i = t; i < SCH * Mq / 2; i += 256) stw[i] = twp[i];
    __syncthreads();

    unsigned long long a[Mq];
    const unsigned long long* Ap = (const unsigned long long*)g_A + (size_t)b * Mq * Dq + d;
#pragma unroll
    for (int k = 0; k < Mq; k++) a[k] = Ap[k * Dq];

    float base_add = cb[d];
    float c0v = g_c0[b * Dq + d], cNv = g_cN[b * Dq + d];
    const float* xa = x   + ((size_t)(b * Sq + s0)) * Dq + d;
    const float* xb = xa + (size_t)Hq * Dq;
    float*       oa = out + ((size_t)(b * Sq + s0)) * Dq + d;
    float*       ob = oa + (size_t)Hq * Dq;

    float va[8], vb[8];
#pragma unroll
    for (int u = 0; u < 8; u++) { va[u] = xa[u * Dq]; vb[u] = xb[u * Dq]; }

#pragma unroll 1
    for (int i0 = 0; i0 < SCH; i0 += 8) {
        int ip = (i0 + 8 < SCH) ? (i0 + 8) : (SCH - 8);   // clamped prefetch
        float na[8], nb[8];
#pragma unroll
        for (int u = 0; u < 8; u++) { na[u] = xa[(ip + u) * Dq]; nb[u] = xb[(ip + u) * Dq]; }
#pragma unroll
        for (int u = 0; u < 8; u++) {
            int i = i0 + u;
            unsigned long long ae = 0ull, ao = 0ull;
#pragma unroll
            for (int k2 = 0; k2 < 8; k2++) {
                ulonglong2 tt = stw[i * 8 + k2];
                asm("fma.rn.f32x2 %0, %1, %2, %0;" : "+l"(ae) : "l"(a[2*k2  ]), "l"(tt.x));
                asm("fma.rn.f32x2 %0, %1, %2, %0;" : "+l"(ao) : "l"(a[2*k2+1]), "l"(tt.y));
            }
            float ex, ey, ox, oy;
            asm("mov.b64 {%0, %1}, %2;" : "=f"(ex), "=f"(ey) : "l"(ae));
            asm("mov.b64 {%0, %1}, %2;" : "=f"(ox), "=f"(oy) : "l"(ao));
            float pe = ex + ey, po = ox + oy;
            float vlo = va[u] + base_add + (pe + po);
            float vhi = vb[u] + base_add + (pe - po);
            int s = s0 + i;
            if (s == 0)      vlo += c0v;   // s = 0
            if (s == Hq - 1) vhi += cNv;   // s+2048 = 4095
            oa[i * Dq] = vlo;
            ob[i * Dq] = vhi;
        }
#pragma unroll
        for (int u = 0; u < 8; u++) { va[u] = na[u]; vb[u] = nb[u]; }
    }
}

// ---------------- launch ----------------
extern "C" void kernel_launch(void* const* d_in, const int* in_sizes, int n_in,
                              void* d_out, int out_size) {
    (void)in_sizes; (void)n_in; (void)out_size;
    const float* x     = (const float*)d_in[0];
    const float* gamma = (const float*)d_in[1];
    const float* beta  = (const float*)d_in[2];
    const float* wr    = (const float*)d_in[3];
    const float* wi    = (const float*)d_in[4];
    const float* cw    = (const float*)d_in[5];
    const float* cb    = (const float*)d_in[6];
    float* out = (float*)d_out;

    twiddle_k<<<(Hq * Mq) / 256, 256>>>();
    tr_k<<<dim3(Dq / 32, Dq / 32), dim3(32, 8)>>>(cw);
    ln_k<<<(Bq * Sq) / 8, 256>>>(x);
    proj_k<<<dim3(NCH, Bq, 2), 256>>>(x, gamma, beta);
    c0a_k<<<dim3(Mq, Bq, 4), 128>>>(wr, wi);
    c0b_k<<<Bq, Dq>>>();
    c1_k<<<dim3(16, 4, Bq), 128>>>();
    c1r_k<<<dim3(Mq, Bq), Dq>>>();
    final_k<<<dim3(NCH, Bq, 2), 256>>>(x, cb, out);
}

// round 8
// speedup vs baseline: 3.1202x; 1.0003x over previous
#include <cuda_runtime.h>

#define Bq 8
#define Sq 4096
#define Hq 2048               // half period
#define Dq 512
#define Mq 16
#define NCH 32
#define SCH (Hq/NCH)          // 64 s_lo rows per chunk
#define INV_S (1.0f/4096.0f)

// ---------------- device scratch (no allocations allowed) ----------------
__device__ __align__(16) float2 g_tw[Hq*Mq];   // per (s,k), s<2048: (cos(w_k s), -sin(w_k s))
__device__ float  g_mu[Bq*Sq];
__device__ float  g_rs[Bq*Sq];
__device__ float2 g_part[NCH*Bq*Mq*Dq];        // partial projections [chunk][b][k][d] (re,im)
__device__ float2 g_D[Bq*Mq*Dq];               // spectral coeffs with w applied [b][k][d]
__device__ float  g_xsf[Bq*Dq];                // xs at s=0   (scaled by 1/S)
__device__ float  g_xsl[Bq*Dq];                // xs at s=S-1 (scaled by 1/S)
__device__ float2 g_A[Bq*Mq*Dq];               // combined scaled coeffs [b][k][d]
__device__ float  g_c0[Bq*Dq];                 // boundary correction at s=0
__device__ float  g_cN[Bq*Dq];                 // boundary correction at s=S-1
// transposed conv weights, [di][dd] layout (coalesced along dd)
__device__ float  g_w1[Dq*Dq];
__device__ float  g_ws[Dq*Dq];                 // w0+w2
__device__ float  g_wd[Dq*Dq];                 // w2-w0
// c1 partials over di-chunks
__device__ float2 g_c1p[4*Bq*Mq*Dq];           // [cc][b][k][dd]
__device__ float2 g_edg[4*Bq*Dq];              // [cc][b][dd] -> (a0, aN)

// ---------------- twiddle table (float sincospi: exact argument) ----------------
__global__ void twiddle_k() {
    int i = blockIdx.x * 256 + threadIdx.x;   // i = s*16 + k, s < 2048
    int s = i >> 4, k = i & 15;
    int ks = (k * s) & (Sq - 1);
    float sf, cf;
    sincospif((float)ks * (1.0f / 2048.0f), &sf, &cf);
    g_tw[i] = make_float2(cf, -sf);
}

// ---------------- transpose conv weights into [di][dd] planes ----------------
__global__ void tr_k(const float* __restrict__ cw) {
    __shared__ float t1[32][33], ts[32][33], td[32][33];
    int di0 = blockIdx.x * 32, dd0 = blockIdx.y * 32;
    int tx = threadIdx.x, ty = threadIdx.y;   // block (32,8)
#pragma unroll
    for (int jj = 0; jj < 4; jj++) {
        int ddl = ty + jj * 8;
        const float* p = cw + ((size_t)(dd0 + ddl) * Dq + di0 + tx) * 3;
        float w0 = p[0], w1 = p[1], w2 = p[2];
        t1[ddl][tx] = w1;
        ts[ddl][tx] = w0 + w2;
        td[ddl][tx] = w2 - w0;
    }
    __syncthreads();
#pragma unroll
    for (int jj = 0; jj < 4; jj++) {
        int dil = ty + jj * 8;
        size_t o = (size_t)(di0 + dil) * Dq + dd0 + tx;
        g_w1[o] = t1[tx][dil];
        g_ws[o] = ts[tx][dil];
        g_wd[o] = td[tx][dil];
    }
}

// ---------------- LayerNorm stats: one warp per (b,s) row ----------------
__global__ void ln_k(const float* __restrict__ x) {
    int lane = threadIdx.x & 31;
    int row  = blockIdx.x * 8 + (threadIdx.x >> 5);   // b*Sq + s
    const float4* xr = (const float4*)(x + (size_t)row * Dq);
    float s1 = 0.f, s2 = 0.f;
#pragma unroll
    for (int it = 0; it < 4; it++) {
        float4 v = xr[lane + it * 32];
        s1 += (v.x + v.y) + (v.z + v.w);
        s2 = fmaf(v.x, v.x, s2); s2 = fmaf(v.y, v.y, s2);
        s2 = fmaf(v.z, v.z, s2); s2 = fmaf(v.w, v.w, s2);
    }
#pragma unroll
    for (int off = 16; off > 0; off >>= 1) {
        s1 += __shfl_xor_sync(0xffffffffu, s1, off);
        s2 += __shfl_xor_sync(0xffffffffu, s2, off);
    }
    if (lane == 0) {
        float mu  = s1 * (1.f / Dq);
        float var = fmaf(-mu, mu, s2 * (1.f / Dq));
        g_mu[row] = mu;
        g_rs[row] = rsqrtf(var + 1e-5f);
    }
}

// ---------------- projection with half-period pairing + depth-8 prefetch pipeline ----------------
// pair (s, s+2048): P_k += (xn_a + (-1)^k xn_b) * e^{-i w_k s}
// grid (NCH, Bq, 2 d-tiles), block 256
__global__ void proj_k(const float* __restrict__ x,
                       const float* __restrict__ gamma,
                       const float* __restrict__ beta) {
    __shared__ ulonglong2 stw[SCH * Mq / 2];   // 8 KB
    __shared__ float smu[2 * SCH], srs[2 * SCH];
    int b = blockIdx.y, ch = blockIdx.x;
    int d = blockIdx.z * 256 + threadIdx.x;
    int t = threadIdx.x;
    int s0 = ch * SCH;
    const ulonglong2* twp = (const ulonglong2*)(g_tw + (size_t)s0 * Mq);
#pragma unroll
    for (int i = t; i < SCH * Mq / 2; i += 256) stw[i] = twp[i];
    int row0 = b * Sq + s0;
    if (t < SCH)            { smu[t] = g_mu[row0 + t];              srs[t] = g_rs[row0 + t]; }
    else if (t < 2 * SCH)   { smu[t] = g_mu[row0 + Hq + (t - SCH)]; srs[t] = g_rs[row0 + Hq + (t - SCH)]; }
    __syncthreads();

    float gm = gamma[d], bt = beta[d];
    unsigned long long acc[Mq];
#pragma unroll
    for (int k = 0; k < Mq; k++) acc[k] = 0ull;

    const float* xa = x + ((size_t)row0) * Dq + d;
    const float* xb = xa + (size_t)Hq * Dq;

    float va[8], vb[8];
#pragma unroll
    for (int u = 0; u < 8; u++) { va[u] = xa[u * Dq]; vb[u] = xb[u * Dq]; }

#pragma unroll 1
    for (int i0 = 0; i0 < SCH; i0 += 8) {
        int ip = (i0 + 8 < SCH) ? (i0 + 8) : (SCH - 8);   // clamped prefetch
        float na[8], nb[8];
#pragma unroll
        for (int u = 0; u < 8; u++) { na[u] = xa[(ip + u) * Dq]; nb[u] = xb[(ip + u) * Dq]; }
#pragma unroll
        for (int u = 0; u < 8; u++) {
            int i = i0 + u;
            float xna = fmaf((va[u] - smu[i]) * srs[i], gm, bt);
            float xnb = fmaf((vb[u] - smu[SCH + i]) * srs[SCH + i], gm, bt);
            float xs = xna + xnb, xd = xna - xnb;
            unsigned long long ps, pd;
            asm("mov.b64 %0, {%1, %1};" : "=l"(ps) : "f"(xs));
            asm("mov.b64 %0, {%1, %1};" : "=l"(pd) : "f"(xd));
#pragma unroll
            for (int k2 = 0; k2 < 8; k2++) {
                ulonglong2 tt = stw[i * 8 + k2];
                asm("fma.rn.f32x2 %0, %1, %2, %0;" : "+l"(acc[2*k2  ]) : "l"(ps), "l"(tt.x));
                asm("fma.rn.f32x2 %0, %1, %2, %0;" : "+l"(acc[2*k2+1]) : "l"(pd), "l"(tt.y));
            }
        }
#pragma unroll
        for (int u = 0; u < 8; u++) { va[u] = na[u]; vb[u] = nb[u]; }
    }
    unsigned long long* pout = (unsigned long long*)g_part + ((size_t)(ch * Bq + b) * Mq) * Dq + d;
#pragma unroll
    for (int k = 0; k < Mq; k++) pout[k * Dq] = acc[k];
}

// ---------------- reduce partials, apply complex spectral weight ----------------
__global__ void c0a_k(const float* __restrict__ wr, const float* __restrict__ wi) {
    int k = blockIdx.x, b = blockIdx.y;
    int d = blockIdx.z * 128 + threadIdx.x;
    const unsigned long long* pp = (const unsigned long long*)g_part;
    unsigned long long s = 0ull;
#pragma unroll
    for (int c = 0; c < NCH; c++) {
        unsigned long long v = pp[((size_t)(c * Bq + b) * Mq + k) * Dq + d];
        asm("add.rn.f32x2 %0, %0, %1;" : "+l"(s) : "l"(v));
    }
    float sr, si;
    asm("mov.b64 {%0, %1}, %2;" : "=f"(sr), "=f"(si) : "l"(s));
    float wrv = wr[d * Mq + k], wiv = wi[d * Mq + k];
    float Dr = sr * wrv - si * wiv;
    float Di = (k == 0) ? 0.f : fmaf(sr, wiv, si * wrv);   // irfft drops Im of bin 0
    g_D[(size_t)(b * Mq + k) * Dq + d] = make_float2(Dr, Di);
}

// ---------------- edge values xs(0), xs(S-1) ----------------
__global__ void c0b_k() {
    int b = blockIdx.x, di = threadIdx.x;
    float xsf = 0.f, xsl = 0.f;
#pragma unroll
    for (int k = 0; k < Mq; k++) {
        float2 Dv = g_D[(size_t)(b * Mq + k) * Dq + di];
        float2 t = g_tw[Mq + k];           // s=1 row: (cos w_k, -sin w_k)
        float ck = t.x, sk = -t.y;
        float m = (k == 0) ? 1.f : 2.f;
        xsf += m * Dv.x;
        xsl += m * (Dv.x * ck + Dv.y * sk);    // Re(D_k e^{-i w_k})
    }
    g_xsf[b * Dq + di] = xsf * INV_S;
    g_xsl[b * Dq + di] = xsl * INV_S;
}

// ---------------- spectral-domain conv partials: coalesced, split over di chunks ----------------
__global__ void c1_k() {
    int kg = blockIdx.x & 3, cc = blockIdx.x >> 2;
    int tile = blockIdx.y, b = blockIdx.z;
    int tid = threadIdx.x;
    int dd = tile * 128 + tid;
    int k0 = kg * 4;
    __shared__ float sDr[4][128], sDi[4][128], sxf[128], sxl[128];

    float ck[4], sk[4];
#pragma unroll
    for (int kk = 0; kk < 4; kk++) {
        float2 t = g_tw[Mq + (k0 + kk)];
        ck[kk] = t.x; sk[kk] = -t.y;
    }
#pragma unroll
    for (int kk = 0; kk < 4; kk++) {
        float2 Dv = g_D[(size_t)(b * Mq + k0 + kk) * Dq + cc * 128 + tid];
        sDr[kk][tid] = Dv.x; sDi[kk][tid] = Dv.y;
    }
    if (kg == 0) {
        sxf[tid] = g_xsf[b * Dq + cc * 128 + tid];
        sxl[tid] = g_xsl[b * Dq + cc * 128 + tid];
    }
    __syncthreads();

    float ar[4] = {0.f,0.f,0.f,0.f}, ai[4] = {0.f,0.f,0.f,0.f};
    float a0 = 0.f, aN = 0.f;
    int dibase = cc * 128;
#pragma unroll 4
    for (int j = 0; j < 128; j++) {
        size_t o = (size_t)(dibase + j) * Dq + dd;
        float w1 = g_w1[o], ws = g_ws[o], wd = g_wd[o];
#pragma unroll
        for (int kk = 0; kk < 4; kk++) {
            float hr = fmaf(ws, ck[kk], w1);
            float hi = wd * sk[kk];
            float Dr = sDr[kk][j], Di = sDi[kk][j];
            ar[kk] = fmaf(hr, Dr, ar[kk]); ar[kk] = fmaf(-hi, Di, ar[kk]);
            ai[kk] = fmaf(hr, Di, ai[kk]); ai[kk] = fmaf( hi, Dr, ai[kk]);
        }
        if (kg == 0) {
            float w0 = 0.5f * (ws - wd), w2 = 0.5f * (ws + wd);
            a0 = fmaf(-w0, sxl[j], a0);   // circular wrap removal at s=0
            aN = fmaf(-w2, sxf[j], aN);   // circular wrap removal at s=S-1
        }
    }
#pragma unroll
    for (int kk = 0; kk < 4; kk++)
        g_c1p[((size_t)(cc * Bq + b) * Mq + k0 + kk) * Dq + dd] = make_float2(ar[kk], ai[kk]);
    if (kg == 0)
        g_edg[(size_t)(cc * Bq + b) * Dq + dd] = make_float2(a0, aN);
}

// ---------------- reduce c1 partials: A_k = sc*(conv + identity), edge sums ----------------
__global__ void c1r_k() {
    int k = blockIdx.x, b = blockIdx.y, d = threadIdx.x;
    float sr = 0.f, si = 0.f;
#pragma unroll
    for (int cc = 0; cc < 4; cc++) {
        float2 v = g_c1p[((size_t)(cc * Bq + b) * Mq + k) * Dq + d];
        sr += v.x; si += v.y;
    }
    float2 Dv = g_D[(size_t)(b * Mq + k) * Dq + d];
    float sc = (k == 0) ? INV_S : 2.f * INV_S;
    g_A[(size_t)(b * Mq + k) * Dq + d] = make_float2(sc * (sr + Dv.x), sc * (si + Dv.y));
    if (k == 0) {
        float e0 = 0.f, eN = 0.f;
#pragma unroll
        for (int cc = 0; cc < 4; cc++) {
            float2 e = g_edg[(size_t)(cc * Bq + b) * Dq + d];
            e0 += e.x; eN += e.y;
        }
        g_c0[b * Dq + d] = e0;
        g_cN[b * Dq + d] = eN;
    }
}

// ---------------- final with half-period pairing + depth-8 prefetch pipeline ----------------
// out(s)      = x(s)      + cb + (pe + po)
// out(s+2048) = x(s+2048) + cb + (pe - po)
// grid (NCH, Bq, 2 d-tiles), block 256
__global__ void final_k(const float* __restrict__ x, const float* __restrict__ cb,
                        float* __restrict__ out) {
    __shared__ ulonglong2 stw[SCH * Mq / 2];
    int b = blockIdx.y, ch = blockIdx.x;
    int d = blockIdx.z * 256 + threadIdx.x;
    int t = threadIdx.x;
    int s0 = ch * SCH;
    const ulonglong2* twp = (const ulonglong2*)(g_tw + (size_t)s0 * Mq);
#pragma unroll
    for (int i = t; i < SCH * Mq / 2; i += 256) stw[i] = twp[i];
    __syncthreads();

    unsigned long long a[Mq];
    const unsigned long long* Ap = (const unsigned long long*)g_A + (size_t)b * Mq * Dq + d;
#pragma unroll
    for (int k = 0; k < Mq; k++) a[k] = Ap[k * Dq];

    float base_add = cb[d];
    float c0v = g_c0[b * Dq + d], cNv = g_cN[b * Dq + d];
    const float* xa = x   + ((size_t)(b * Sq + s0)) * Dq + d;
    const float* xb = xa + (size_t)Hq * Dq;
    float*       oa = out + ((size_t)(b * Sq + s0)) * Dq + d;
    float*       ob = oa + (size_t)Hq * Dq;

    float va[8], vb[8];
#pragma unroll
    for (int u = 0; u < 8; u++) { va[u] = xa[u * Dq]; vb[u] = xb[u * Dq]; }

#pragma unroll 1
    for (int i0 = 0; i0 < SCH; i0 += 8) {
        int ip = (i0 + 8 < SCH) ? (i0 + 8) : (SCH - 8);   // clamped prefetch
        float na[8], nb[8];
#pragma unroll
        for (int u = 0; u < 8; u++) { na[u] = xa[(ip + u) * Dq]; nb[u] = xb[(ip + u) * Dq]; }
#pragma unroll
        for (int u = 0; u < 8; u++) {
            int i = i0 + u;
            unsigned long long ae = 0ull, ao = 0ull;
#pragma unroll
            for (int k2 = 0; k2 < 8; k2++) {
                ulonglong2 tt = stw[i * 8 + k2];
                asm("fma.rn.f32x2 %0, %1, %2, %0;" : "+l"(ae) : "l"(a[2*k2  ]), "l"(tt.x));
                asm("fma.rn.f32x2 %0, %1, %2, %0;" : "+l"(ao) : "l"(a[2*k2+1]), "l"(tt.y));
            }
            float ex, ey, ox, oy;
            asm("mov.b64 {%0, %1}, %2;" : "=f"(ex), "=f"(ey) : "l"(ae));
            asm("mov.b64 {%0, %1}, %2;" : "=f"(ox), "=f"(oy) : "l"(ao));
            float pe = ex + ey, po = ox + oy;
            float vlo = va[u] + base_add + (pe + po);
            float vhi = vb[u] + base_add + (pe - po);
            int s = s0 + i;
            if (s == 0)      vlo += c0v;   // s = 0
            if (s == Hq - 1) vhi += cNv;   // s+2048 = 4095
            oa[i * Dq] = vlo;
            ob[i * Dq] = vhi;
        }
#pragma unroll
        for (int u = 0; u < 8; u++) { va[u] = na[u]; vb[u] = nb[u]; }
    }
}

// ---------------- launch ----------------
extern "C" void kernel_launch(void* const* d_in, const int* in_sizes, int n_in,
                              void* d_out, int out_size) {
    (void)in_sizes; (void)n_in; (void)out_size;
    const float* x     = (const float*)d_in[0];
    const float* gamma = (const float*)d_in[1];
    const float* beta  = (const float*)d_in[2];
    const float* wr    = (const float*)d_in[3];
    const float* wi    = (const float*)d_in[4];
    const float* cw    = (const float*)d_in[5];
    const float* cb    = (const float*)d_in[6];
    float* out = (float*)d_out;

    twiddle_k<<<(Hq * Mq) / 256, 256>>>();
    tr_k<<<dim3(Dq / 32, Dq / 32), dim3(32, 8)>>>(cw);
    ln_k<<<(Bq * Sq) / 8, 256>>>(x);
    proj_k<<<dim3(NCH, Bq, 2), 256>>>(x, gamma, beta);
    c0a_k<<<dim3(Mq, Bq, 4), 128>>>(wr, wi);
    c0b_k<<<Bq, Dq>>>();
    c1_k<<<dim3(16, 4, Bq), 128>>>();
    c1r_k<<<dim3(Mq, Bq), Dq>>>();
    final_k<<<dim3(NCH, Bq, 2), 256>>>(x, cb, out);
}